// round 3
// baseline (speedup 1.0000x reference)
#include <cuda_runtime.h>
#include <math.h>

// Problem constants
#define BATCH   4
#define NSEQ    2048
#define CDIM    768
#define NHEADS  12
#define DH      64
#define H3      2304      // 3*CDIM
#define HID     3072      // 4*CDIM
#define MDIM    (BATCH*NSEQ)   // 8192 rows

// -------------------- scratch (no allocations allowed) --------------------
__device__ float g_h   [MDIM * CDIM];   // LN1 out
__device__ float g_qkv [MDIM * H3];     // qkv projection
__device__ float g_attn[MDIM * CDIM];   // attention out (pre-proj)
__device__ float g_x1  [MDIM * CDIM];   // residual 1
__device__ float g_h2  [MDIM * CDIM];   // LN2 out
__device__ float g_mlp [MDIM * HID];    // fc1 out (post-gelu)

// -------------------- LayerNorm: one block per row --------------------
__global__ __launch_bounds__(256)
void ln_kernel(const float* __restrict__ x,
               const float* __restrict__ w,
               const float* __restrict__ b,
               float* __restrict__ y) {
    int row = blockIdx.x;
    const float* xr = x + (size_t)row * CDIM;
    int t = threadIdx.x;            // 256 threads, 3 elems each (768)
    float v0 = xr[t], v1 = xr[t + 256], v2 = xr[t + 512];
    float s  = v0 + v1 + v2;
    float ss = v0*v0 + v1*v1 + v2*v2;
    #pragma unroll
    for (int o = 16; o > 0; o >>= 1) {
        s  += __shfl_xor_sync(0xffffffffu, s,  o);
        ss += __shfl_xor_sync(0xffffffffu, ss, o);
    }
    __shared__ float sh_s[8], sh_ss[8];
    __shared__ float sh_mean, sh_rstd;
    int warp = t >> 5, lane = t & 31;
    if (lane == 0) { sh_s[warp] = s; sh_ss[warp] = ss; }
    __syncthreads();
    if (t == 0) {
        float ts = 0.f, tss = 0.f;
        #pragma unroll
        for (int i = 0; i < 8; i++) { ts += sh_s[i]; tss += sh_ss[i]; }
        float mean = ts * (1.0f / CDIM);
        float var  = tss * (1.0f / CDIM) - mean * mean;
        sh_mean = mean;
        sh_rstd = rsqrtf(var + 1e-5f);
    }
    __syncthreads();
    float mean = sh_mean, r = sh_rstd;
    float* yr = y + (size_t)row * CDIM;
    yr[t]       = (v0 - mean) * r * w[t]       + b[t];
    yr[t + 256] = (v1 - mean) * r * w[t + 256] + b[t + 256];
    yr[t + 512] = (v2 - mean) * r * w[t + 512] + b[t + 512];
}

// -------------------- GEMM: Y[M,N] = X[M,K] @ W[N,K]^T (+epilogue) ------
// EPI: 0 = none, 2 = +bias+residual, 3 = +bias+gelu(exact erf)
template<int EPI>
__global__ __launch_bounds__(256)
void gemm_kernel(const float* __restrict__ X,
                 const float* __restrict__ W,
                 const float* __restrict__ bias,
                 const float* __restrict__ res,
                 float* __restrict__ Y,
                 int Nout, int K) {
    __shared__ float As[16 * 65];   // [kk][m] padded
    __shared__ float Bs[16 * 65];   // [kk][n] padded
    int t  = threadIdx.x;
    int tx = t & 15, ty = t >> 4;
    int m0 = blockIdx.y * 64, n0 = blockIdx.x * 64;

    float acc[4][4] = {};

    int lr = t >> 2;          // 0..63 : row within tile
    int lk = (t & 3) * 4;     // 0,4,8,12 : k offset
    const float* Xp = X + (size_t)(m0 + lr) * K + lk;
    const float* Wp = W + (size_t)(n0 + lr) * K + lk;

    for (int k0 = 0; k0 < K; k0 += 16) {
        float4 a  = *(const float4*)(Xp + k0);
        float4 bv = *(const float4*)(Wp + k0);
        __syncthreads();
        As[(lk + 0) * 65 + lr] = a.x;
        As[(lk + 1) * 65 + lr] = a.y;
        As[(lk + 2) * 65 + lr] = a.z;
        As[(lk + 3) * 65 + lr] = a.w;
        Bs[(lk + 0) * 65 + lr] = bv.x;
        Bs[(lk + 1) * 65 + lr] = bv.y;
        Bs[(lk + 2) * 65 + lr] = bv.z;
        Bs[(lk + 3) * 65 + lr] = bv.w;
        __syncthreads();
        #pragma unroll
        for (int kk = 0; kk < 16; kk++) {
            float av[4], bw[4];
            #pragma unroll
            for (int i = 0; i < 4; i++) av[i] = As[kk * 65 + ty * 4 + i];
            #pragma unroll
            for (int j = 0; j < 4; j++) bw[j] = Bs[kk * 65 + tx * 4 + j];
            #pragma unroll
            for (int i = 0; i < 4; i++)
                #pragma unroll
                for (int j = 0; j < 4; j++)
                    acc[i][j] += av[i] * bw[j];
        }
    }

    float4 b4 = make_float4(0.f, 0.f, 0.f, 0.f);
    if (EPI >= 2) b4 = *(const float4*)(bias + n0 + tx * 4);

    #pragma unroll
    for (int i = 0; i < 4; i++) {
        int row = m0 + ty * 4 + i;
        size_t off = (size_t)row * Nout + n0 + tx * 4;
        float v[4] = { acc[i][0], acc[i][1], acc[i][2], acc[i][3] };
        if (EPI >= 2) { v[0] += b4.x; v[1] += b4.y; v[2] += b4.z; v[3] += b4.w; }
        if (EPI == 2) {
            float4 rv = *(const float4*)(res + off);
            v[0] += rv.x; v[1] += rv.y; v[2] += rv.z; v[3] += rv.w;
        }
        if (EPI == 3) {
            #pragma unroll
            for (int j = 0; j < 4; j++)
                v[j] = 0.5f * v[j] * (1.0f + erff(v[j] * 0.70710678118654752f));
        }
        *(float4*)(Y + off) = make_float4(v[0], v[1], v[2], v[3]);
    }
}

// -------------------- Flash attention: 64-query tiles --------------------
// grid: (NSEQ/64, BATCH*NHEADS), 256 threads, dynamic smem 49408 B
__global__ __launch_bounds__(256)
void attn_kernel(const float* __restrict__ qkv,
                 float* __restrict__ out) {
    extern __shared__ float sm[];
    float* Qs = sm;              // [64][64]
    float* KP = sm + 64 * 64;    // [64][65]  K tile, reused for P
    float* Vs = KP + 64 * 65;    // [64][64]

    int bh = blockIdx.y;
    int b  = bh / NHEADS, hh = bh % NHEADS;
    int q0 = blockIdx.x * 64;
    int t  = threadIdx.x;
    int tx = t & 15, ty = t >> 4;
    const float scale = 0.125f;  // 1/sqrt(64)

    for (int idx = t; idx < 64 * 64; idx += 256) {
        int r = idx >> 6, d = idx & 63;
        Qs[r * 64 + d] =
            qkv[(size_t)(b * NSEQ + q0 + r) * H3 + hh * 64 + d] * scale;
    }

    float o[4][4] = {};
    float m[4], l[4] = {};
    #pragma unroll
    for (int i = 0; i < 4; i++) m[i] = -1e30f;

    for (int j0 = 0; j0 < NSEQ; j0 += 64) {
        __syncthreads();  // prior readers of KP/Vs done
        for (int idx = t; idx < 64 * 64; idx += 256) {
            int r = idx >> 6, d = idx & 63;
            size_t g = (size_t)(b * NSEQ + j0 + r) * H3 + hh * 64 + d;
            KP[r * 65 + d] = qkv[g + CDIM];        // K
            Vs[r * 64 + d] = qkv[g + 2 * CDIM];    // V
        }
        __syncthreads();

        float s[4][4] = {};
        #pragma unroll 8
        for (int d = 0; d < 64; d++) {
            float qv[4], kv[4];
            #pragma unroll
            for (int i = 0; i < 4; i++) qv[i] = Qs[(ty * 4 + i) * 64 + d];
            #pragma unroll
            for (int j = 0; j < 4; j++) kv[j] = KP[(tx * 4 + j) * 65 + d];
            #pragma unroll
            for (int i = 0; i < 4; i++)
                #pragma unroll
                for (int j = 0; j < 4; j++)
                    s[i][j] += qv[i] * kv[j];
        }

        // online softmax over this key tile (row owned by 16 lanes: xor 8,4,2,1)
        #pragma unroll
        for (int i = 0; i < 4; i++) {
            float mx = fmaxf(fmaxf(s[i][0], s[i][1]), fmaxf(s[i][2], s[i][3]));
            #pragma unroll
            for (int off = 8; off > 0; off >>= 1)
                mx = fmaxf(mx, __shfl_xor_sync(0xffffffffu, mx, off));
            float mnew = fmaxf(m[i], mx);
            float alpha = __expf(m[i] - mnew);
            float rs = 0.f;
            #pragma unroll
            for (int j = 0; j < 4; j++) {
                s[i][j] = __expf(s[i][j] - mnew);
                rs += s[i][j];
            }
            #pragma unroll
            for (int off = 8; off > 0; off >>= 1)
                rs += __shfl_xor_sync(0xffffffffu, rs, off);
            l[i] = l[i] * alpha + rs;
            m[i] = mnew;
            #pragma unroll
            for (int j = 0; j < 4; j++) o[i][j] *= alpha;
        }

        __syncthreads();  // everyone done reading K from KP
        #pragma unroll
        for (int i = 0; i < 4; i++)
            #pragma unroll
            for (int j = 0; j < 4; j++)
                KP[(ty * 4 + i) * 65 + tx * 4 + j] = s[i][j];
        __syncthreads();

        #pragma unroll 8
        for (int kk = 0; kk < 64; kk++) {
            float pv[4], vv[4];
            #pragma unroll
            for (int i = 0; i < 4; i++) pv[i] = KP[(ty * 4 + i) * 65 + kk];
            #pragma unroll
            for (int j = 0; j < 4; j++) vv[j] = Vs[kk * 64 + tx * 4 + j];
            #pragma unroll
            for (int i = 0; i < 4; i++)
                #pragma unroll
                for (int j = 0; j < 4; j++)
                    o[i][j] += pv[i] * vv[j];
        }
    }

    #pragma unroll
    for (int i = 0; i < 4; i++) {
        float inv = 1.0f / l[i];
        int row = q0 + ty * 4 + i;
        #pragma unroll
        for (int j = 0; j < 4; j++)
            out[(size_t)(b * NSEQ + row) * CDIM + hh * 64 + tx * 4 + j] =
                o[i][j] * inv;
    }
}

// -------------------- launch --------------------
#define ATTN_SMEM ((64*64 + 64*65 + 64*64) * 4)

extern "C" void kernel_launch(void* const* d_in, const int* in_sizes, int n_in,
                              void* d_out, int out_size) {
    const float* x      = (const float*)d_in[0];
    const float* qkv_w  = (const float*)d_in[1];
    const float* proj_w = (const float*)d_in[2];
    const float* proj_b = (const float*)d_in[3];
    const float* n1w    = (const float*)d_in[4];
    const float* n1b    = (const float*)d_in[5];
    const float* n2w    = (const float*)d_in[6];
    const float* n2b    = (const float*)d_in[7];
    const float* fc1w   = (const float*)d_in[8];
    const float* fc1b   = (const float*)d_in[9];
    const float* fc2w   = (const float*)d_in[10];
    const float* fc2b   = (const float*)d_in[11];
    float* out = (float*)d_out;

    static bool s_init = false;
    static float *h, *qkv, *attn, *attn_o, *x1, *h2, *mlp;
    if (!s_init) {
        cudaGetSymbolAddress((void**)&h,      g_h);
        cudaGetSymbolAddress((void**)&qkv,    g_qkv);
        cudaGetSymbolAddress((void**)&attn_o, g_attn);
        cudaGetSymbolAddress((void**)&x1,     g_x1);
        cudaGetSymbolAddress((void**)&h2,     g_h2);
        cudaGetSymbolAddress((void**)&mlp,    g_mlp);
        cudaFuncSetAttribute(attn_kernel,
                             cudaFuncAttributeMaxDynamicSharedMemorySize,
                             ATTN_SMEM);
        s_init = true;
    }
    (void)attn; (void)in_sizes; (void)n_in; (void)out_size;

    dim3 thr(256);

    // 1. LN1
    ln_kernel<<<MDIM, thr>>>(x, n1w, n1b, h);
    // 2. qkv = h @ qkv_w^T   (no bias)
    gemm_kernel<0><<<dim3(H3 / 64, MDIM / 64), thr>>>(h, qkv_w, nullptr, nullptr,
                                                      qkv, H3, CDIM);
    // 3. attention
    attn_kernel<<<dim3(NSEQ / 64, BATCH * NHEADS), thr, ATTN_SMEM>>>(qkv, attn_o);
    // 4. x1 = x + attn_o @ proj_w^T + proj_b
    gemm_kernel<2><<<dim3(CDIM / 64, MDIM / 64), thr>>>(attn_o, proj_w, proj_b, x,
                                                        x1, CDIM, CDIM);
    // 5. LN2
    ln_kernel<<<MDIM, thr>>>(x1, n2w, n2b, h2);
    // 6. mlp = gelu(h2 @ fc1_w^T + fc1_b)
    gemm_kernel<3><<<dim3(HID / 64, MDIM / 64), thr>>>(h2, fc1w, fc1b, nullptr,
                                                       mlp, HID, CDIM);
    // 7. out = x1 + mlp @ fc2_w^T + fc2_b
    gemm_kernel<2><<<dim3(CDIM / 64, MDIM / 64), thr>>>(mlp, fc2w, fc2b, x1,
                                                        out, CDIM, HID);
}

// round 4
// speedup vs baseline: 1.2803x; 1.2803x over previous
#include <cuda_runtime.h>
#include <math.h>

// Problem constants
#define BATCH   4
#define NSEQ    2048
#define CDIM    768
#define NHEADS  12
#define DH      64
#define H3      2304      // 3*CDIM
#define HID     3072      // 4*CDIM
#define MDIM    (BATCH*NSEQ)   // 8192 rows

// -------------------- scratch (no allocations allowed) --------------------
__device__ float g_h   [MDIM * CDIM];   // LN1 out
__device__ float g_qkv [MDIM * H3];     // qkv projection
__device__ float g_attn[MDIM * CDIM];   // attention out (pre-proj)
__device__ float g_x1  [MDIM * CDIM];   // residual 1
__device__ float g_h2  [MDIM * CDIM];   // LN2 out
__device__ float g_mlp [MDIM * HID];    // fc1 out (post-gelu)

// -------------------- LayerNorm: one block per row --------------------
__global__ __launch_bounds__(256)
void ln_kernel(const float* __restrict__ x,
               const float* __restrict__ w,
               const float* __restrict__ b,
               float* __restrict__ y) {
    int row = blockIdx.x;
    const float* xr = x + (size_t)row * CDIM;
    int t = threadIdx.x;            // 256 threads, 3 elems each (768)
    float v0 = xr[t], v1 = xr[t + 256], v2 = xr[t + 512];
    float s  = v0 + v1 + v2;
    float ss = v0*v0 + v1*v1 + v2*v2;
    #pragma unroll
    for (int o = 16; o > 0; o >>= 1) {
        s  += __shfl_xor_sync(0xffffffffu, s,  o);
        ss += __shfl_xor_sync(0xffffffffu, ss, o);
    }
    __shared__ float sh_s[8], sh_ss[8];
    __shared__ float sh_mean, sh_rstd;
    int warp = t >> 5, lane = t & 31;
    if (lane == 0) { sh_s[warp] = s; sh_ss[warp] = ss; }
    __syncthreads();
    if (t == 0) {
        float ts = 0.f, tss = 0.f;
        #pragma unroll
        for (int i = 0; i < 8; i++) { ts += sh_s[i]; tss += sh_ss[i]; }
        float mean = ts * (1.0f / CDIM);
        float var  = tss * (1.0f / CDIM) - mean * mean;
        sh_mean = mean;
        sh_rstd = rsqrtf(var + 1e-5f);
    }
    __syncthreads();
    float mean = sh_mean, r = sh_rstd;
    float* yr = y + (size_t)row * CDIM;
    yr[t]       = (v0 - mean) * r * w[t]       + b[t];
    yr[t + 256] = (v1 - mean) * r * w[t + 256] + b[t + 256];
    yr[t + 512] = (v2 - mean) * r * w[t + 512] + b[t + 512];
}

// ---------- GEMM 128x128x8, 8x8/thread, double-buffered ----------
// Y[M,N] = X[M,K] @ W[N,K]^T (+epilogue)
// EPI: 0 = none, 2 = +bias+residual, 3 = +bias+gelu(exact erf)
template<int EPI>
__global__ __launch_bounds__(256)
void gemm128(const float* __restrict__ X,
             const float* __restrict__ W,
             const float* __restrict__ bias,
             const float* __restrict__ res,
             float* __restrict__ Y,
             int Nout, int K) {
    __shared__ float As[2][8][128];
    __shared__ float Bs[2][8][128];
    int t  = threadIdx.x;
    int tx = t & 15, ty = t >> 4;          // 16 x 16 thread grid
    int m0 = blockIdx.y * 128, n0 = blockIdx.x * 128;

    int lrow = t >> 1;            // 0..127 : row within tile
    int lk   = (t & 1) * 4;       // 0 or 4 : k offset

    const float* Xp = X + (size_t)(m0 + lrow) * K + lk;
    const float* Wp = W + (size_t)(n0 + lrow) * K + lk;

    float acc[8][8] = {};

    // preload tile 0
    {
        float4 a = *(const float4*)(Xp);
        float4 b = *(const float4*)(Wp);
        As[0][lk + 0][lrow] = a.x; As[0][lk + 1][lrow] = a.y;
        As[0][lk + 2][lrow] = a.z; As[0][lk + 3][lrow] = a.w;
        Bs[0][lk + 0][lrow] = b.x; Bs[0][lk + 1][lrow] = b.y;
        Bs[0][lk + 2][lrow] = b.z; Bs[0][lk + 3][lrow] = b.w;
    }
    __syncthreads();

    int buf = 0;
    for (int k0 = 8; k0 < K; k0 += 8) {
        // prefetch next tile from global into registers
        float4 na = *(const float4*)(Xp + k0);
        float4 nb = *(const float4*)(Wp + k0);

        #pragma unroll
        for (int kk = 0; kk < 8; kk++) {
            float av[8], bv[8];
            *(float4*)&av[0] = *(const float4*)&As[buf][kk][ty * 8];
            *(float4*)&av[4] = *(const float4*)&As[buf][kk][ty * 8 + 4];
            *(float4*)&bv[0] = *(const float4*)&Bs[buf][kk][tx * 8];
            *(float4*)&bv[4] = *(const float4*)&Bs[buf][kk][tx * 8 + 4];
            #pragma unroll
            for (int i = 0; i < 8; i++)
                #pragma unroll
                for (int j = 0; j < 8; j++)
                    acc[i][j] += av[i] * bv[j];
        }

        int nb_buf = buf ^ 1;
        As[nb_buf][lk + 0][lrow] = na.x; As[nb_buf][lk + 1][lrow] = na.y;
        As[nb_buf][lk + 2][lrow] = na.z; As[nb_buf][lk + 3][lrow] = na.w;
        Bs[nb_buf][lk + 0][lrow] = nb.x; Bs[nb_buf][lk + 1][lrow] = nb.y;
        Bs[nb_buf][lk + 2][lrow] = nb.z; Bs[nb_buf][lk + 3][lrow] = nb.w;
        __syncthreads();
        buf = nb_buf;
    }

    // last tile
    #pragma unroll
    for (int kk = 0; kk < 8; kk++) {
        float av[8], bv[8];
        *(float4*)&av[0] = *(const float4*)&As[buf][kk][ty * 8];
        *(float4*)&av[4] = *(const float4*)&As[buf][kk][ty * 8 + 4];
        *(float4*)&bv[0] = *(const float4*)&Bs[buf][kk][tx * 8];
        *(float4*)&bv[4] = *(const float4*)&Bs[buf][kk][tx * 8 + 4];
        #pragma unroll
        for (int i = 0; i < 8; i++)
            #pragma unroll
            for (int j = 0; j < 8; j++)
                acc[i][j] += av[i] * bv[j];
    }

    // epilogue: 8 rows x 8 cols per thread (two float4 per row)
    float bz[8];
    if (EPI >= 2) {
        *(float4*)&bz[0] = *(const float4*)(bias + n0 + tx * 8);
        *(float4*)&bz[4] = *(const float4*)(bias + n0 + tx * 8 + 4);
    }

    #pragma unroll
    for (int i = 0; i < 8; i++) {
        int row = m0 + ty * 8 + i;
        size_t off = (size_t)row * Nout + n0 + tx * 8;
        float v[8];
        #pragma unroll
        for (int j = 0; j < 8; j++) v[j] = acc[i][j];
        if (EPI >= 2) {
            #pragma unroll
            for (int j = 0; j < 8; j++) v[j] += bz[j];
        }
        if (EPI == 2) {
            float4 r0 = *(const float4*)(res + off);
            float4 r1 = *(const float4*)(res + off + 4);
            v[0] += r0.x; v[1] += r0.y; v[2] += r0.z; v[3] += r0.w;
            v[4] += r1.x; v[5] += r1.y; v[6] += r1.z; v[7] += r1.w;
        }
        if (EPI == 3) {
            #pragma unroll
            for (int j = 0; j < 8; j++)
                v[j] = 0.5f * v[j] * (1.0f + erff(v[j] * 0.70710678118654752f));
        }
        *(float4*)(Y + off)     = make_float4(v[0], v[1], v[2], v[3]);
        *(float4*)(Y + off + 4) = make_float4(v[4], v[5], v[6], v[7]);
    }
}

// -------------------- Flash attention: 64-query tiles --------------------
// grid: (NSEQ/64, BATCH*NHEADS), 256 threads, dynamic smem 49408 B
__global__ __launch_bounds__(256)
void attn_kernel(const float* __restrict__ qkv,
                 float* __restrict__ out) {
    extern __shared__ float sm[];
    float* Qs = sm;              // [64][64]
    float* KP = sm + 64 * 64;    // [64][65]  K tile, reused for P
    float* Vs = KP + 64 * 65;    // [64][64]

    int bh = blockIdx.y;
    int b  = bh / NHEADS, hh = bh % NHEADS;
    int q0 = blockIdx.x * 64;
    int t  = threadIdx.x;
    int tx = t & 15, ty = t >> 4;
    const float scale = 0.125f;  // 1/sqrt(64)

    for (int idx = t; idx < 64 * 64; idx += 256) {
        int r = idx >> 6, d = idx & 63;
        Qs[r * 64 + d] =
            qkv[(size_t)(b * NSEQ + q0 + r) * H3 + hh * 64 + d] * scale;
    }

    float o[4][4] = {};
    float m[4], l[4] = {};
    #pragma unroll
    for (int i = 0; i < 4; i++) m[i] = -1e30f;

    for (int j0 = 0; j0 < NSEQ; j0 += 64) {
        __syncthreads();  // prior readers of KP/Vs done
        for (int idx = t; idx < 64 * 64; idx += 256) {
            int r = idx >> 6, d = idx & 63;
            size_t g = (size_t)(b * NSEQ + j0 + r) * H3 + hh * 64 + d;
            KP[r * 65 + d] = qkv[g + CDIM];        // K
            Vs[r * 64 + d] = qkv[g + 2 * CDIM];    // V
        }
        __syncthreads();

        float s[4][4] = {};
        #pragma unroll 8
        for (int d = 0; d < 64; d++) {
            float qv[4], kv[4];
            #pragma unroll
            for (int i = 0; i < 4; i++) qv[i] = Qs[(ty * 4 + i) * 64 + d];
            #pragma unroll
            for (int j = 0; j < 4; j++) kv[j] = KP[(tx * 4 + j) * 65 + d];
            #pragma unroll
            for (int i = 0; i < 4; i++)
                #pragma unroll
                for (int j = 0; j < 4; j++)
                    s[i][j] += qv[i] * kv[j];
        }

        // online softmax over this key tile
        #pragma unroll
        for (int i = 0; i < 4; i++) {
            float mx = fmaxf(fmaxf(s[i][0], s[i][1]), fmaxf(s[i][2], s[i][3]));
            #pragma unroll
            for (int off = 8; off > 0; off >>= 1)
                mx = fmaxf(mx, __shfl_xor_sync(0xffffffffu, mx, off));
            float mnew = fmaxf(m[i], mx);
            float alpha = __expf(m[i] - mnew);
            float rs = 0.f;
            #pragma unroll
            for (int j = 0; j < 4; j++) {
                s[i][j] = __expf(s[i][j] - mnew);
                rs += s[i][j];
            }
            #pragma unroll
            for (int off = 8; off > 0; off >>= 1)
                rs += __shfl_xor_sync(0xffffffffu, rs, off);
            l[i] = l[i] * alpha + rs;
            m[i] = mnew;
            #pragma unroll
            for (int j = 0; j < 4; j++) o[i][j] *= alpha;
        }

        __syncthreads();  // everyone done reading K from KP
        #pragma unroll
        for (int i = 0; i < 4; i++)
            #pragma unroll
            for (int j = 0; j < 4; j++)
                KP[(ty * 4 + i) * 65 + tx * 4 + j] = s[i][j];
        __syncthreads();

        #pragma unroll 8
        for (int kk = 0; kk < 64; kk++) {
            float pv[4], vv[4];
            #pragma unroll
            for (int i = 0; i < 4; i++) pv[i] = KP[(ty * 4 + i) * 65 + kk];
            #pragma unroll
            for (int j = 0; j < 4; j++) vv[j] = Vs[kk * 64 + tx * 4 + j];
            #pragma unroll
            for (int i = 0; i < 4; i++)
                #pragma unroll
                for (int j = 0; j < 4; j++)
                    o[i][j] += pv[i] * vv[j];
        }
    }

    #pragma unroll
    for (int i = 0; i < 4; i++) {
        float inv = 1.0f / l[i];
        int row = q0 + ty * 4 + i;
        #pragma unroll
        for (int j = 0; j < 4; j++)
            out[(size_t)(b * NSEQ + row) * CDIM + hh * 64 + tx * 4 + j] =
                o[i][j] * inv;
    }
}

// -------------------- launch --------------------
#define ATTN_SMEM ((64*64 + 64*65 + 64*64) * 4)

extern "C" void kernel_launch(void* const* d_in, const int* in_sizes, int n_in,
                              void* d_out, int out_size) {
    const float* x      = (const float*)d_in[0];
    const float* qkv_w  = (const float*)d_in[1];
    const float* proj_w = (const float*)d_in[2];
    const float* proj_b = (const float*)d_in[3];
    const float* n1w    = (const float*)d_in[4];
    const float* n1b    = (const float*)d_in[5];
    const float* n2w    = (const float*)d_in[6];
    const float* n2b    = (const float*)d_in[7];
    const float* fc1w   = (const float*)d_in[8];
    const float* fc1b   = (const float*)d_in[9];
    const float* fc2w   = (const float*)d_in[10];
    const float* fc2b   = (const float*)d_in[11];
    float* out = (float*)d_out;

    static bool s_init = false;
    static float *h, *qkv, *attn_o, *x1, *h2, *mlp;
    if (!s_init) {
        cudaGetSymbolAddress((void**)&h,      g_h);
        cudaGetSymbolAddress((void**)&qkv,    g_qkv);
        cudaGetSymbolAddress((void**)&attn_o, g_attn);
        cudaGetSymbolAddress((void**)&x1,     g_x1);
        cudaGetSymbolAddress((void**)&h2,     g_h2);
        cudaGetSymbolAddress((void**)&mlp,    g_mlp);
        cudaFuncSetAttribute(attn_kernel,
                             cudaFuncAttributeMaxDynamicSharedMemorySize,
                             ATTN_SMEM);
        s_init = true;
    }
    (void)in_sizes; (void)n_in; (void)out_size;

    dim3 thr(256);

    // 1. LN1
    ln_kernel<<<MDIM, thr>>>(x, n1w, n1b, h);
    // 2. qkv = h @ qkv_w^T   (no bias)
    gemm128<0><<<dim3(H3 / 128, MDIM / 128), thr>>>(h, qkv_w, nullptr, nullptr,
                                                    qkv, H3, CDIM);
    // 3. attention
    attn_kernel<<<dim3(NSEQ / 64, BATCH * NHEADS), thr, ATTN_SMEM>>>(qkv, attn_o);
    // 4. x1 = x + attn_o @ proj_w^T + proj_b
    gemm128<2><<<dim3(CDIM / 128, MDIM / 128), thr>>>(attn_o, proj_w, proj_b, x,
                                                      x1, CDIM, CDIM);
    // 5. LN2
    ln_kernel<<<MDIM, thr>>>(x1, n2w, n2b, h2);
    // 6. mlp = gelu(h2 @ fc1_w^T + fc1_b)
    gemm128<3><<<dim3(HID / 128, MDIM / 128), thr>>>(h2, fc1w, fc1b, nullptr,
                                                     mlp, HID, CDIM);
    // 7. out = x1 + mlp @ fc2_w^T + fc2_b
    gemm128<2><<<dim3(CDIM / 128, MDIM / 128), thr>>>(mlp, fc2w, fc2b, x1,
                                                      out, CDIM, HID);
}

// round 7
// speedup vs baseline: 2.0517x; 1.6026x over previous
#include <cuda_runtime.h>
#include <cuda_bf16.h>
#include <math.h>
#include <stdint.h>

// Problem constants
#define BATCH   4
#define NSEQ    2048
#define CDIM    768
#define NHEADS  12
#define H3      2304      // 3*CDIM
#define HID     3072      // 4*CDIM
#define MDIM    (BATCH*NSEQ)   // 8192 rows

// -------------------- scratch (no allocations allowed) --------------------
__device__ __nv_bfloat16 g_xhi[MDIM * CDIM], g_xlo[MDIM * CDIM];  // LN out (h, later h2)
__device__ float         g_qkv[MDIM * H3];                        // qkv (fp32, attn input)
__device__ __nv_bfloat16 g_ahi[MDIM * CDIM], g_alo[MDIM * CDIM];  // attn out
__device__ float         g_x1 [MDIM * CDIM];                      // residual 1
__device__ __nv_bfloat16 g_mhi[MDIM * HID],  g_mlo[MDIM * HID];   // mlp (post-gelu)
__device__ __nv_bfloat16 g_wqkvh[H3 * CDIM],  g_wqkvl[H3 * CDIM];
__device__ __nv_bfloat16 g_wprjh[CDIM * CDIM], g_wprjl[CDIM * CDIM];
__device__ __nv_bfloat16 g_wf1h[HID * CDIM],  g_wf1l[HID * CDIM];
__device__ __nv_bfloat16 g_wf2h[CDIM * HID],  g_wf2l[CDIM * HID];

// -------------------- small helpers --------------------
__device__ __forceinline__ void split2(float x, __nv_bfloat16& hi, __nv_bfloat16& lo) {
    hi = __float2bfloat16_rn(x);
    lo = __float2bfloat16_rn(x - __bfloat162float(hi));
}
__device__ __forceinline__ void cp_async16(uint32_t dst, const void* src) {
    asm volatile("cp.async.cg.shared.global [%0], [%1], 16;\n" :: "r"(dst), "l"(src));
}
__device__ __forceinline__ void cp_commit() {
    asm volatile("cp.async.commit_group;\n");
}
template<int N> __device__ __forceinline__ void cp_wait() {
    asm volatile("cp.async.wait_group %0;\n" :: "n"(N));
}
__device__ __forceinline__ void ldm_x4(uint32_t& r0, uint32_t& r1, uint32_t& r2, uint32_t& r3,
                                       uint32_t addr) {
    asm volatile("ldmatrix.sync.aligned.m8n8.x4.shared.b16 {%0,%1,%2,%3},[%4];\n"
                 : "=r"(r0), "=r"(r1), "=r"(r2), "=r"(r3) : "r"(addr));
}
__device__ __forceinline__ void ldm_x2(uint32_t& r0, uint32_t& r1, uint32_t addr) {
    asm volatile("ldmatrix.sync.aligned.m8n8.x2.shared.b16 {%0,%1},[%2];\n"
                 : "=r"(r0), "=r"(r1) : "r"(addr));
}
__device__ __forceinline__ void mma16816(float* c, uint32_t a0, uint32_t a1, uint32_t a2,
                                         uint32_t a3, uint32_t b0, uint32_t b1) {
    asm volatile("mma.sync.aligned.m16n8k16.row.col.f32.bf16.bf16.f32 "
                 "{%0,%1,%2,%3},{%4,%5,%6,%7},{%8,%9},{%0,%1,%2,%3};\n"
                 : "+f"(c[0]), "+f"(c[1]), "+f"(c[2]), "+f"(c[3])
                 : "r"(a0), "r"(a1), "r"(a2), "r"(a3), "r"(b0), "r"(b1));
}

// -------------------- weight split: fp32 -> bf16 hi/lo --------------------
__global__ __launch_bounds__(256)
void wconv_kernel(const float* __restrict__ w,
                  __nv_bfloat16* __restrict__ hi,
                  __nv_bfloat16* __restrict__ lo, int n4) {
    int i = blockIdx.x * blockDim.x + threadIdx.x;
    if (i >= n4) return;
    float4 v = ((const float4*)w)[i];
    __nv_bfloat16 h0, l0, h1, l1, h2, l2, h3, l3;
    split2(v.x, h0, l0); split2(v.y, h1, l1);
    split2(v.z, h2, l2); split2(v.w, h3, l3);
    ((__nv_bfloat162*)hi)[i * 2]     = __nv_bfloat162(h0, h1);
    ((__nv_bfloat162*)hi)[i * 2 + 1] = __nv_bfloat162(h2, h3);
    ((__nv_bfloat162*)lo)[i * 2]     = __nv_bfloat162(l0, l1);
    ((__nv_bfloat162*)lo)[i * 2 + 1] = __nv_bfloat162(l2, l3);
}

// -------------------- LayerNorm -> bf16 hi/lo --------------------
__global__ __launch_bounds__(256)
void ln_kernel(const float* __restrict__ x,
               const float* __restrict__ w,
               const float* __restrict__ b,
               __nv_bfloat16* __restrict__ yhi,
               __nv_bfloat16* __restrict__ ylo) {
    int row = blockIdx.x;
    const float* xr = x + (size_t)row * CDIM;
    int t = threadIdx.x;
    float v0 = xr[t], v1 = xr[t + 256], v2 = xr[t + 512];
    float s  = v0 + v1 + v2;
    float ss = v0*v0 + v1*v1 + v2*v2;
    #pragma unroll
    for (int o = 16; o > 0; o >>= 1) {
        s  += __shfl_xor_sync(0xffffffffu, s,  o);
        ss += __shfl_xor_sync(0xffffffffu, ss, o);
    }
    __shared__ float sh_s[8], sh_ss[8];
    __shared__ float sh_mean, sh_rstd;
    int warp = t >> 5, lane = t & 31;
    if (lane == 0) { sh_s[warp] = s; sh_ss[warp] = ss; }
    __syncthreads();
    if (t == 0) {
        float ts = 0.f, tss = 0.f;
        #pragma unroll
        for (int i = 0; i < 8; i++) { ts += sh_s[i]; tss += sh_ss[i]; }
        float mean = ts * (1.0f / CDIM);
        float var  = tss * (1.0f / CDIM) - mean * mean;
        sh_mean = mean;
        sh_rstd = rsqrtf(var + 1e-5f);
    }
    __syncthreads();
    float mean = sh_mean, r = sh_rstd;
    size_t base = (size_t)row * CDIM;
    #pragma unroll
    for (int p = 0; p < 3; p++) {
        int c = t + p * 256;
        float v = (p == 0) ? v0 : (p == 1) ? v1 : v2;
        float y = (v - mean) * r * w[c] + b[c];
        __nv_bfloat16 hi, lo;
        split2(y, hi, lo);
        yhi[base + c] = hi;
        ylo[base + c] = lo;
    }
}

// ========== tensor-core GEMM: Y[M,N] = X[M,K] @ W[N,K]^T (3-term bf16 split) ====
// EPI: 0 = none, 2 = +bias+residual, 3 = +bias+gelu    OUT: 0 = fp32, 1 = bf16 hi/lo
#define LDP   40                 // padded row stride (bf16 elems)
#define TILE  (128 * LDP)        // one operand tile in smem (elems)
#define STAGE (4 * TILE)         // Ahi,Alo,Bhi,Blo
#define GSMEM (2 * STAGE * 2)    // bytes (2 stages, bf16)

template<int EPI, int OUT>
__global__ __launch_bounds__(256)
void gemm_tc(const __nv_bfloat16* __restrict__ Ahi, const __nv_bfloat16* __restrict__ Alo,
             const __nv_bfloat16* __restrict__ Bhi, const __nv_bfloat16* __restrict__ Blo,
             const float* __restrict__ bias, const float* __restrict__ res,
             float* __restrict__ Y,
             __nv_bfloat16* __restrict__ Yhi, __nv_bfloat16* __restrict__ Ylo,
             int Nout, int K) {
    extern __shared__ __align__(16) char smem_raw[];
    uint32_t sbase = (uint32_t)__cvta_generic_to_shared(smem_raw);

    const int t = threadIdx.x, lane = t & 31, warp = t >> 5;
    const int wm = (warp & 1) * 64;    // warp m-offset in tile
    const int wn = (warp >> 1) * 32;   // warp n-offset in tile
    const int m0 = blockIdx.y * 128, n0 = blockIdx.x * 128;

    float acc[4][4][4] = {};   // [m-frag][n-frag][c0..c3]

    // stage loader: 4 tiles x 512 chunks of 16B, 8 cp.async per thread
    auto issue = [&](int s, int k0) {
        uint32_t so = sbase + (uint32_t)(s * STAGE) * 2;
        #pragma unroll
        for (int p = 0; p < 2; p++) {
            int idx = t + p * 256;          // 0..511
            int row = idx >> 2;
            int c8  = (idx & 3) * 8;        // bf16 col offset
            size_t ga = (size_t)(m0 + row) * K + k0 + c8;
            size_t gb = (size_t)(n0 + row) * K + k0 + c8;
            uint32_t sm = (uint32_t)(row * LDP + c8) * 2;
            cp_async16(so + 0 * TILE * 2 + sm, Ahi + ga);
            cp_async16(so + 1 * TILE * 2 + sm, Alo + ga);
            cp_async16(so + 2 * TILE * 2 + sm, Bhi + gb);
            cp_async16(so + 3 * TILE * 2 + sm, Blo + gb);
        }
        cp_commit();
    };

    issue(0, 0);
    const int KT = K / 32;
    for (int kt = 0; kt < KT; kt++) {
        if (kt + 1 < KT) { issue((kt + 1) & 1, (kt + 1) * 32); cp_wait<1>(); }
        else             { cp_wait<0>(); }
        __syncthreads();

        uint32_t so = sbase + (uint32_t)((kt & 1) * STAGE) * 2;
        #pragma unroll
        for (int ks = 0; ks < 2; ks++) {
            // A fragments (hi & lo): 4 m-frags
            uint32_t ahi[4][4], alo[4][4];
            #pragma unroll
            for (int i = 0; i < 4; i++) {
                uint32_t off = (uint32_t)((wm + i * 16 + (lane & 15)) * LDP +
                                          ks * 16 + (lane >> 4) * 8) * 2;
                ldm_x4(ahi[i][0], ahi[i][1], ahi[i][2], ahi[i][3], so + 0 * TILE * 2 + off);
                ldm_x4(alo[i][0], alo[i][1], alo[i][2], alo[i][3], so + 1 * TILE * 2 + off);
            }
            // B fragments: 4 n-frags
            uint32_t bhi[4][2], blo[4][2];
            #pragma unroll
            for (int j = 0; j < 4; j++) {
                int q = lane & 15;
                uint32_t off = (uint32_t)((wn + j * 8 + (q & 7)) * LDP +
                                          ks * 16 + (q >> 3) * 8) * 2;
                ldm_x2(bhi[j][0], bhi[j][1], so + 2 * TILE * 2 + off);
                ldm_x2(blo[j][0], blo[j][1], so + 3 * TILE * 2 + off);
            }
            #pragma unroll
            for (int i = 0; i < 4; i++)
                #pragma unroll
                for (int j = 0; j < 4; j++) {
                    mma16816(acc[i][j], ahi[i][0], ahi[i][1], ahi[i][2], ahi[i][3],
                             bhi[j][0], bhi[j][1]);
                    mma16816(acc[i][j], ahi[i][0], ahi[i][1], ahi[i][2], ahi[i][3],
                             blo[j][0], blo[j][1]);
                    mma16816(acc[i][j], alo[i][0], alo[i][1], alo[i][2], alo[i][3],
                             bhi[j][0], bhi[j][1]);
                }
        }
        __syncthreads();
    }

    // ---- epilogue ----
    const int g = lane >> 2, tig = lane & 3;
    #pragma unroll
    for (int i = 0; i < 4; i++) {
        int rowa = m0 + wm + i * 16 + g;
        #pragma unroll
        for (int j = 0; j < 4; j++) {
            int coln = n0 + wn + j * 8 + tig * 2;
            float v[4] = { acc[i][j][0], acc[i][j][1], acc[i][j][2], acc[i][j][3] };
            if (EPI >= 2) {
                float b0 = bias[coln], b1 = bias[coln + 1];
                v[0] += b0; v[1] += b1; v[2] += b0; v[3] += b1;
            }
            size_t off0 = (size_t)rowa * Nout + coln;
            size_t off1 = (size_t)(rowa + 8) * Nout + coln;
            if (EPI == 2) {
                float2 r0 = *(const float2*)(res + off0);
                float2 r1 = *(const float2*)(res + off1);
                v[0] += r0.x; v[1] += r0.y; v[2] += r1.x; v[3] += r1.y;
            }
            if (EPI == 3) {
                #pragma unroll
                for (int e = 0; e < 4; e++)
                    v[e] = 0.5f * v[e] * (1.0f + erff(v[e] * 0.70710678118654752f));
            }
            if (OUT == 0) {
                *(float2*)(Y + off0) = make_float2(v[0], v[1]);
                *(float2*)(Y + off1) = make_float2(v[2], v[3]);
            } else {
                __nv_bfloat16 h0, l0, h1, l1, h2, l2, h3, l3;
                split2(v[0], h0, l0); split2(v[1], h1, l1);
                split2(v[2], h2, l2); split2(v[3], h3, l3);
                *(__nv_bfloat162*)(Yhi + off0) = __nv_bfloat162(h0, h1);
                *(__nv_bfloat162*)(Yhi + off1) = __nv_bfloat162(h2, h3);
                *(__nv_bfloat162*)(Ylo + off0) = __nv_bfloat162(l0, l1);
                *(__nv_bfloat162*)(Ylo + off1) = __nv_bfloat162(l2, l3);
            }
        }
    }
}

// -------------------- Flash attention (fp32), writes bf16 hi/lo --------------------
__global__ __launch_bounds__(256)
void attn_kernel(const float* __restrict__ qkv,
                 __nv_bfloat16* __restrict__ ohi,
                 __nv_bfloat16* __restrict__ olo) {
    extern __shared__ float sm[];
    float* Qs = sm;              // [64][64]
    float* KP = sm + 64 * 64;    // [64][65]  K tile, reused for P
    float* Vs = KP + 64 * 65;    // [64][64]

    int bh = blockIdx.y;
    int b  = bh / NHEADS, hh = bh % NHEADS;
    int q0 = blockIdx.x * 64;
    int t  = threadIdx.x;
    int tx = t & 15, ty = t >> 4;
    const float scale = 0.125f;  // 1/sqrt(64)

    for (int idx = t; idx < 64 * 64; idx += 256) {
        int r = idx >> 6, d = idx & 63;
        Qs[r * 64 + d] =
            qkv[(size_t)(b * NSEQ + q0 + r) * H3 + hh * 64 + d] * scale;
    }

    float o[4][4] = {};
    float m[4], l[4] = {};
    #pragma unroll
    for (int i = 0; i < 4; i++) m[i] = -1e30f;

    for (int j0 = 0; j0 < NSEQ; j0 += 64) {
        __syncthreads();
        for (int idx = t; idx < 64 * 64; idx += 256) {
            int r = idx >> 6, d = idx & 63;
            size_t gidx = (size_t)(b * NSEQ + j0 + r) * H3 + hh * 64 + d;
            KP[r * 65 + d] = qkv[gidx + CDIM];        // K
            Vs[r * 64 + d] = qkv[gidx + 2 * CDIM];    // V
        }
        __syncthreads();

        float s[4][4] = {};
        #pragma unroll 8
        for (int d = 0; d < 64; d++) {
            float qv[4], kv[4];
            #pragma unroll
            for (int i = 0; i < 4; i++) qv[i] = Qs[(ty * 4 + i) * 64 + d];
            #pragma unroll
            for (int j = 0; j < 4; j++) kv[j] = KP[(tx * 4 + j) * 65 + d];
            #pragma unroll
            for (int i = 0; i < 4; i++)
                #pragma unroll
                for (int j = 0; j < 4; j++)
                    s[i][j] += qv[i] * kv[j];
        }

        #pragma unroll
        for (int i = 0; i < 4; i++) {
            float mx = fmaxf(fmaxf(s[i][0], s[i][1]), fmaxf(s[i][2], s[i][3]));
            #pragma unroll
            for (int off = 8; off > 0; off >>= 1)
                mx = fmaxf(mx, __shfl_xor_sync(0xffffffffu, mx, off));
            float mnew = fmaxf(m[i], mx);
            float alpha = __expf(m[i] - mnew);
            float rs = 0.f;
            #pragma unroll
            for (int j = 0; j < 4; j++) {
                s[i][j] = __expf(s[i][j] - mnew);
                rs += s[i][j];
            }
            #pragma unroll
            for (int off = 8; off > 0; off >>= 1)
                rs += __shfl_xor_sync(0xffffffffu, rs, off);
            l[i] = l[i] * alpha + rs;
            m[i] = mnew;
            #pragma unroll
            for (int j = 0; j < 4; j++) o[i][j] *= alpha;
        }

        __syncthreads();
        #pragma unroll
        for (int i = 0; i < 4; i++)
            #pragma unroll
            for (int j = 0; j < 4; j++)
                KP[(ty * 4 + i) * 65 + tx * 4 + j] = s[i][j];
        __syncthreads();

        #pragma unroll 8
        for (int kk = 0; kk < 64; kk++) {
            float pv[4], vv[4];
            #pragma unroll
            for (int i = 0; i < 4; i++) pv[i] = KP[(ty * 4 + i) * 65 + kk];
            #pragma unroll
            for (int j = 0; j < 4; j++) vv[j] = Vs[kk * 64 + tx * 4 + j];
            #pragma unroll
            for (int i = 0; i < 4; i++)
                #pragma unroll
                for (int j = 0; j < 4; j++)
                    o[i][j] += pv[i] * vv[j];
        }
    }

    #pragma unroll
    for (int i = 0; i < 4; i++) {
        float inv = 1.0f / l[i];
        int row = q0 + ty * 4 + i;
        size_t base = (size_t)(b * NSEQ + row) * CDIM + hh * 64 + tx * 4;
        #pragma unroll
        for (int j = 0; j < 4; j++) {
            __nv_bfloat16 hi, lo;
            split2(o[i][j] * inv, hi, lo);
            ohi[base + j] = hi;
            olo[base + j] = lo;
        }
    }
}

// -------------------- launch --------------------
#define ATTN_SMEM ((64*64 + 64*65 + 64*64) * 4)

extern "C" void kernel_launch(void* const* d_in, const int* in_sizes, int n_in,
                              void* d_out, int out_size) {
    const float* x      = (const float*)d_in[0];
    const float* qkv_w  = (const float*)d_in[1];
    const float* proj_w = (const float*)d_in[2];
    const float* proj_b = (const float*)d_in[3];
    const float* n1w    = (const float*)d_in[4];
    const float* n1b    = (const float*)d_in[5];
    const float* n2w    = (const float*)d_in[6];
    const float* n2b    = (const float*)d_in[7];
    const float* fc1w   = (const float*)d_in[8];
    const float* fc1b   = (const float*)d_in[9];
    const float* fc2w   = (const float*)d_in[10];
    const float* fc2b   = (const float*)d_in[11];
    float* out = (float*)d_out;

    static bool s_init = false;
    static __nv_bfloat16 *xhi, *xlo, *ahi, *alo, *mhi, *mlo;
    static __nv_bfloat16 *wqh, *wql, *wph, *wpl, *w1h, *w1l, *w2h, *w2l;
    static float *qkv, *x1;
    if (!s_init) {
        cudaGetSymbolAddress((void**)&xhi, g_xhi);
        cudaGetSymbolAddress((void**)&xlo, g_xlo);
        cudaGetSymbolAddress((void**)&qkv, g_qkv);
        cudaGetSymbolAddress((void**)&ahi, g_ahi);
        cudaGetSymbolAddress((void**)&alo, g_alo);
        cudaGetSymbolAddress((void**)&x1,  g_x1);
        cudaGetSymbolAddress((void**)&mhi, g_mhi);
        cudaGetSymbolAddress((void**)&mlo, g_mlo);
        cudaGetSymbolAddress((void**)&wqh, g_wqkvh);
        cudaGetSymbolAddress((void**)&wql, g_wqkvl);
        cudaGetSymbolAddress((void**)&wph, g_wprjh);
        cudaGetSymbolAddress((void**)&wpl, g_wprjl);
        cudaGetSymbolAddress((void**)&w1h, g_wf1h);
        cudaGetSymbolAddress((void**)&w1l, g_wf1l);
        cudaGetSymbolAddress((void**)&w2h, g_wf2h);
        cudaGetSymbolAddress((void**)&w2l, g_wf2l);
        cudaFuncSetAttribute(attn_kernel,
                             cudaFuncAttributeMaxDynamicSharedMemorySize, ATTN_SMEM);
        cudaFuncSetAttribute(gemm_tc<0,0>,
                             cudaFuncAttributeMaxDynamicSharedMemorySize, GSMEM);
        cudaFuncSetAttribute(gemm_tc<2,0>,
                             cudaFuncAttributeMaxDynamicSharedMemorySize, GSMEM);
        cudaFuncSetAttribute(gemm_tc<3,1>,
                             cudaFuncAttributeMaxDynamicSharedMemorySize, GSMEM);
        s_init = true;
    }
    (void)in_sizes; (void)n_in; (void)out_size;

    dim3 thr(256);

    // weight splits (every call: stateless/deterministic)
    wconv_kernel<<<(H3*CDIM/4 + 255)/256, thr>>>(qkv_w,  wqh, wql, H3*CDIM/4);
    wconv_kernel<<<(CDIM*CDIM/4 + 255)/256, thr>>>(proj_w, wph, wpl, CDIM*CDIM/4);
    wconv_kernel<<<(HID*CDIM/4 + 255)/256, thr>>>(fc1w,  w1h, w1l, HID*CDIM/4);
    wconv_kernel<<<(CDIM*HID/4 + 255)/256, thr>>>(fc2w,  w2h, w2l, CDIM*HID/4);

    // 1. LN1 -> hi/lo
    ln_kernel<<<MDIM, thr>>>(x, n1w, n1b, xhi, xlo);
    // 2. qkv = h @ qkv_w^T
    gemm_tc<0,0><<<dim3(H3/128, MDIM/128), thr, GSMEM>>>(
        xhi, xlo, wqh, wql, nullptr, nullptr, qkv, nullptr, nullptr, H3, CDIM);
    // 3. attention -> hi/lo
    attn_kernel<<<dim3(NSEQ/64, BATCH*NHEADS), thr, ATTN_SMEM>>>(qkv, ahi, alo);
    // 4. x1 = x + attn @ proj_w^T + proj_b
    gemm_tc<2,0><<<dim3(CDIM/128, MDIM/128), thr, GSMEM>>>(
        ahi, alo, wph, wpl, proj_b, x, x1, nullptr, nullptr, CDIM, CDIM);
    // 5. LN2 -> hi/lo
    ln_kernel<<<MDIM, thr>>>(x1, n2w, n2b, xhi, xlo);
    // 6. mlp = gelu(h2 @ fc1_w^T + fc1_b) -> hi/lo
    gemm_tc<3,1><<<dim3(HID/128, MDIM/128), thr, GSMEM>>>(
        xhi, xlo, w1h, w1l, fc1b, nullptr, nullptr, mhi, mlo, HID, CDIM);
    // 7. out = x1 + mlp @ fc2_w^T + fc2_b
    gemm_tc<2,0><<<dim3(CDIM/128, MDIM/128), thr, GSMEM>>>(
        mhi, mlo, w2h, w2l, fc2b, x1, out, nullptr, nullptr, CDIM, HID);
}

// round 8
// speedup vs baseline: 3.3059x; 1.6113x over previous
#include <cuda_runtime.h>
#include <cuda_bf16.h>
#include <math.h>
#include <stdint.h>

// Problem constants
#define BATCH   4
#define NSEQ    2048
#define CDIM    768
#define NHEADS  12
#define H3      2304      // 3*CDIM
#define HID     3072      // 4*CDIM
#define MDIM    (BATCH*NSEQ)   // 8192 rows

// -------------------- scratch (no allocations allowed) --------------------
__device__ __nv_bfloat16 g_xhi[MDIM * CDIM], g_xlo[MDIM * CDIM];  // LN out
__device__ __nv_bfloat16 g_qkvh[MDIM * H3],  g_qkvl[MDIM * H3];   // qkv hi/lo
__device__ __nv_bfloat16 g_ahi[MDIM * CDIM], g_alo[MDIM * CDIM];  // attn out
__device__ float         g_x1 [MDIM * CDIM];                      // residual 1
__device__ __nv_bfloat16 g_mhi[MDIM * HID],  g_mlo[MDIM * HID];   // mlp (post-gelu)
__device__ __nv_bfloat16 g_wqkvh[H3 * CDIM],  g_wqkvl[H3 * CDIM];
__device__ __nv_bfloat16 g_wprjh[CDIM * CDIM], g_wprjl[CDIM * CDIM];
__device__ __nv_bfloat16 g_wf1h[HID * CDIM],  g_wf1l[HID * CDIM];
__device__ __nv_bfloat16 g_wf2h[CDIM * HID],  g_wf2l[CDIM * HID];

// -------------------- small helpers --------------------
__device__ __forceinline__ void split2(float x, __nv_bfloat16& hi, __nv_bfloat16& lo) {
    hi = __float2bfloat16_rn(x);
    lo = __float2bfloat16_rn(x - __bfloat162float(hi));
}
__device__ __forceinline__ void split_pack2(float x, float y, uint32_t& hi, uint32_t& lo) {
    __nv_bfloat16 hx, lx, hy, ly;
    split2(x, hx, lx); split2(y, hy, ly);
    __nv_bfloat162 H(hx, hy), L(lx, ly);
    hi = *(uint32_t*)&H; lo = *(uint32_t*)&L;
}
__device__ __forceinline__ void cp_async16(uint32_t dst, const void* src) {
    asm volatile("cp.async.cg.shared.global [%0], [%1], 16;\n" :: "r"(dst), "l"(src));
}
__device__ __forceinline__ void cp_commit() {
    asm volatile("cp.async.commit_group;\n");
}
template<int N> __device__ __forceinline__ void cp_wait() {
    asm volatile("cp.async.wait_group %0;\n" :: "n"(N));
}
__device__ __forceinline__ void ldm_x4(uint32_t& r0, uint32_t& r1, uint32_t& r2, uint32_t& r3,
                                       uint32_t addr) {
    asm volatile("ldmatrix.sync.aligned.m8n8.x4.shared.b16 {%0,%1,%2,%3},[%4];\n"
                 : "=r"(r0), "=r"(r1), "=r"(r2), "=r"(r3) : "r"(addr));
}
__device__ __forceinline__ void ldm_x4_t(uint32_t& r0, uint32_t& r1, uint32_t& r2, uint32_t& r3,
                                         uint32_t addr) {
    asm volatile("ldmatrix.sync.aligned.m8n8.x4.trans.shared.b16 {%0,%1,%2,%3},[%4];\n"
                 : "=r"(r0), "=r"(r1), "=r"(r2), "=r"(r3) : "r"(addr));
}
__device__ __forceinline__ void ldm_x2(uint32_t& r0, uint32_t& r1, uint32_t addr) {
    asm volatile("ldmatrix.sync.aligned.m8n8.x2.shared.b16 {%0,%1},[%2];\n"
                 : "=r"(r0), "=r"(r1) : "r"(addr));
}
__device__ __forceinline__ void mma16816(float* c, uint32_t a0, uint32_t a1, uint32_t a2,
                                         uint32_t a3, uint32_t b0, uint32_t b1) {
    asm volatile("mma.sync.aligned.m16n8k16.row.col.f32.bf16.bf16.f32 "
                 "{%0,%1,%2,%3},{%4,%5,%6,%7},{%8,%9},{%0,%1,%2,%3};\n"
                 : "+f"(c[0]), "+f"(c[1]), "+f"(c[2]), "+f"(c[3])
                 : "r"(a0), "r"(a1), "r"(a2), "r"(a3), "r"(b0), "r"(b1));
}

// -------------------- weight split: fp32 -> bf16 hi/lo --------------------
__global__ __launch_bounds__(256)
void wconv_kernel(const float* __restrict__ w,
                  __nv_bfloat16* __restrict__ hi,
                  __nv_bfloat16* __restrict__ lo, int n4) {
    int i = blockIdx.x * blockDim.x + threadIdx.x;
    if (i >= n4) return;
    float4 v = ((const float4*)w)[i];
    __nv_bfloat16 h0, l0, h1, l1, h2, l2, h3, l3;
    split2(v.x, h0, l0); split2(v.y, h1, l1);
    split2(v.z, h2, l2); split2(v.w, h3, l3);
    ((__nv_bfloat162*)hi)[i * 2]     = __nv_bfloat162(h0, h1);
    ((__nv_bfloat162*)hi)[i * 2 + 1] = __nv_bfloat162(h2, h3);
    ((__nv_bfloat162*)lo)[i * 2]     = __nv_bfloat162(l0, l1);
    ((__nv_bfloat162*)lo)[i * 2 + 1] = __nv_bfloat162(l2, l3);
}

// -------------------- LayerNorm -> bf16 hi/lo --------------------
__global__ __launch_bounds__(256)
void ln_kernel(const float* __restrict__ x,
               const float* __restrict__ w,
               const float* __restrict__ b,
               __nv_bfloat16* __restrict__ yhi,
               __nv_bfloat16* __restrict__ ylo) {
    int row = blockIdx.x;
    const float* xr = x + (size_t)row * CDIM;
    int t = threadIdx.x;
    float v0 = xr[t], v1 = xr[t + 256], v2 = xr[t + 512];
    float s  = v0 + v1 + v2;
    float ss = v0*v0 + v1*v1 + v2*v2;
    #pragma unroll
    for (int o = 16; o > 0; o >>= 1) {
        s  += __shfl_xor_sync(0xffffffffu, s,  o);
        ss += __shfl_xor_sync(0xffffffffu, ss, o);
    }
    __shared__ float sh_s[8], sh_ss[8];
    __shared__ float sh_mean, sh_rstd;
    int warp = t >> 5, lane = t & 31;
    if (lane == 0) { sh_s[warp] = s; sh_ss[warp] = ss; }
    __syncthreads();
    if (t == 0) {
        float ts = 0.f, tss = 0.f;
        #pragma unroll
        for (int i = 0; i < 8; i++) { ts += sh_s[i]; tss += sh_ss[i]; }
        float mean = ts * (1.0f / CDIM);
        float var  = tss * (1.0f / CDIM) - mean * mean;
        sh_mean = mean;
        sh_rstd = rsqrtf(var + 1e-5f);
    }
    __syncthreads();
    float mean = sh_mean, r = sh_rstd;
    size_t base = (size_t)row * CDIM;
    #pragma unroll
    for (int p = 0; p < 3; p++) {
        int c = t + p * 256;
        float v = (p == 0) ? v0 : (p == 1) ? v1 : v2;
        float y = (v - mean) * r * w[c] + b[c];
        __nv_bfloat16 hi, lo;
        split2(y, hi, lo);
        yhi[base + c] = hi;
        ylo[base + c] = lo;
    }
}

// ========== tensor-core GEMM: Y[M,N] = X[M,K] @ W[N,K]^T (3-term bf16 split) ====
// EPI: 0 = none, 2 = +bias+residual, 3 = +bias+gelu    OUT: 0 = fp32, 1 = bf16 hi/lo
#define LDP   40                 // padded row stride (bf16 elems)
#define TILE  (128 * LDP)        // one operand tile in smem (elems)
#define STAGE (4 * TILE)         // Ahi,Alo,Bhi,Blo
#define GSMEM (2 * STAGE * 2)    // bytes (2 stages, bf16)

template<int EPI, int OUT>
__global__ __launch_bounds__(256)
void gemm_tc(const __nv_bfloat16* __restrict__ Ahi, const __nv_bfloat16* __restrict__ Alo,
             const __nv_bfloat16* __restrict__ Bhi, const __nv_bfloat16* __restrict__ Blo,
             const float* __restrict__ bias, const float* __restrict__ res,
             float* __restrict__ Y,
             __nv_bfloat16* __restrict__ Yhi, __nv_bfloat16* __restrict__ Ylo,
             int Nout, int K) {
    extern __shared__ __align__(16) char smem_raw[];
    uint32_t sbase = (uint32_t)__cvta_generic_to_shared(smem_raw);

    const int t = threadIdx.x, lane = t & 31, warp = t >> 5;
    const int wm = (warp & 1) * 64;    // warp m-offset in tile
    const int wn = (warp >> 1) * 32;   // warp n-offset in tile
    const int m0 = blockIdx.y * 128, n0 = blockIdx.x * 128;

    float acc[4][4][4] = {};   // [m-frag][n-frag][c0..c3]

    auto issue = [&](int s, int k0) {
        uint32_t so = sbase + (uint32_t)(s * STAGE) * 2;
        #pragma unroll
        for (int p = 0; p < 2; p++) {
            int idx = t + p * 256;          // 0..511
            int row = idx >> 2;
            int c8  = (idx & 3) * 8;        // bf16 col offset
            size_t ga = (size_t)(m0 + row) * K + k0 + c8;
            size_t gb = (size_t)(n0 + row) * K + k0 + c8;
            uint32_t sm = (uint32_t)(row * LDP + c8) * 2;
            cp_async16(so + 0 * TILE * 2 + sm, Ahi + ga);
            cp_async16(so + 1 * TILE * 2 + sm, Alo + ga);
            cp_async16(so + 2 * TILE * 2 + sm, Bhi + gb);
            cp_async16(so + 3 * TILE * 2 + sm, Blo + gb);
        }
        cp_commit();
    };

    issue(0, 0);
    const int KT = K / 32;
    for (int kt = 0; kt < KT; kt++) {
        if (kt + 1 < KT) { issue((kt + 1) & 1, (kt + 1) * 32); cp_wait<1>(); }
        else             { cp_wait<0>(); }
        __syncthreads();

        uint32_t so = sbase + (uint32_t)((kt & 1) * STAGE) * 2;
        #pragma unroll
        for (int ks = 0; ks < 2; ks++) {
            uint32_t ahi[4][4], alo[4][4];
            #pragma unroll
            for (int i = 0; i < 4; i++) {
                uint32_t off = (uint32_t)((wm + i * 16 + (lane & 15)) * LDP +
                                          ks * 16 + (lane >> 4) * 8) * 2;
                ldm_x4(ahi[i][0], ahi[i][1], ahi[i][2], ahi[i][3], so + 0 * TILE * 2 + off);
                ldm_x4(alo[i][0], alo[i][1], alo[i][2], alo[i][3], so + 1 * TILE * 2 + off);
            }
            uint32_t bhi[4][2], blo[4][2];
            #pragma unroll
            for (int j = 0; j < 4; j++) {
                int q = lane & 15;
                uint32_t off = (uint32_t)((wn + j * 8 + (q & 7)) * LDP +
                                          ks * 16 + (q >> 3) * 8) * 2;
                ldm_x2(bhi[j][0], bhi[j][1], so + 2 * TILE * 2 + off);
                ldm_x2(blo[j][0], blo[j][1], so + 3 * TILE * 2 + off);
            }
            #pragma unroll
            for (int i = 0; i < 4; i++)
                #pragma unroll
                for (int j = 0; j < 4; j++) {
                    mma16816(acc[i][j], ahi[i][0], ahi[i][1], ahi[i][2], ahi[i][3],
                             bhi[j][0], bhi[j][1]);
                    mma16816(acc[i][j], ahi[i][0], ahi[i][1], ahi[i][2], ahi[i][3],
                             blo[j][0], blo[j][1]);
                    mma16816(acc[i][j], alo[i][0], alo[i][1], alo[i][2], alo[i][3],
                             bhi[j][0], bhi[j][1]);
                }
        }
        __syncthreads();
    }

    // ---- epilogue ----
    const int g = lane >> 2, tig = lane & 3;
    #pragma unroll
    for (int i = 0; i < 4; i++) {
        int rowa = m0 + wm + i * 16 + g;
        #pragma unroll
        for (int j = 0; j < 4; j++) {
            int coln = n0 + wn + j * 8 + tig * 2;
            float v[4] = { acc[i][j][0], acc[i][j][1], acc[i][j][2], acc[i][j][3] };
            if (EPI >= 2) {
                float b0 = bias[coln], b1 = bias[coln + 1];
                v[0] += b0; v[1] += b1; v[2] += b0; v[3] += b1;
            }
            size_t off0 = (size_t)rowa * Nout + coln;
            size_t off1 = (size_t)(rowa + 8) * Nout + coln;
            if (EPI == 2) {
                float2 r0 = *(const float2*)(res + off0);
                float2 r1 = *(const float2*)(res + off1);
                v[0] += r0.x; v[1] += r0.y; v[2] += r1.x; v[3] += r1.y;
            }
            if (EPI == 3) {
                #pragma unroll
                for (int e = 0; e < 4; e++)
                    v[e] = 0.5f * v[e] * (1.0f + erff(v[e] * 0.70710678118654752f));
            }
            if (OUT == 0) {
                *(float2*)(Y + off0) = make_float2(v[0], v[1]);
                *(float2*)(Y + off1) = make_float2(v[2], v[3]);
            } else {
                uint32_t h01, l01, h23, l23;
                split_pack2(v[0], v[1], h01, l01);
                split_pack2(v[2], v[3], h23, l23);
                *(uint32_t*)(Yhi + off0) = h01;
                *(uint32_t*)(Yhi + off1) = h23;
                *(uint32_t*)(Ylo + off0) = l01;
                *(uint32_t*)(Ylo + off1) = l23;
            }
        }
    }
}

// ========== tensor-core flash attention (bf16 hi/lo split) ==========
// CTA: 128 q-rows, 8 warps (16 rows each), 64-key tiles, 2-stage K/V pipeline.
#define ALDP 72                         // padded row (64 d + 8)
#define QS_BYTES  (128 * ALDP * 2)      // one Q array
#define KV_BYTES  (64 * ALDP * 2)       // one K or V array
#define ATTN_SMEM (2 * QS_BYTES + 2 * 4 * KV_BYTES)   // 110592 B

__global__ __launch_bounds__(256)
void attn_tc(const __nv_bfloat16* __restrict__ qh_g,
             const __nv_bfloat16* __restrict__ ql_g,
             __nv_bfloat16* __restrict__ ohi,
             __nv_bfloat16* __restrict__ olo) {
    extern __shared__ __align__(16) char smem_raw[];
    uint32_t sb = (uint32_t)__cvta_generic_to_shared(smem_raw);
    const int t = threadIdx.x, lane = t & 31, warp = t >> 5;
    const int bidx = blockIdx.y;
    const int b = bidx / NHEADS, hh = bidx % NHEADS;
    const int q0 = blockIdx.x * 128;
    const uint32_t QHI = sb, QLO = sb + QS_BYTES;

    // ---- issue Q (grouped with KV stage 0) ----
    #pragma unroll
    for (int p = 0; p < 4; p++) {
        int idx = t + p * 256;          // 0..1023
        int row = idx >> 3, ch = idx & 7;
        size_t g = (size_t)(b * NSEQ + q0 + row) * H3 + hh * 64 + ch * 8;
        uint32_t so = (uint32_t)(row * ALDP + ch * 8) * 2;
        cp_async16(QHI + so, qh_g + g);
        cp_async16(QLO + so, ql_g + g);
    }
    auto issueKV = [&](int s, int j0) {
        uint32_t base = sb + 2 * QS_BYTES + (uint32_t)s * 4 * KV_BYTES;
        #pragma unroll
        for (int p = 0; p < 2; p++) {
            int idx = t + p * 256;      // 0..511
            int row = idx >> 3, ch = idx & 7;
            size_t gk = (size_t)(b * NSEQ + j0 + row) * H3 + CDIM + hh * 64 + ch * 8;
            size_t gv = gk + CDIM;
            uint32_t so = (uint32_t)(row * ALDP + ch * 8) * 2;
            cp_async16(base + 0 * KV_BYTES + so, qh_g + gk);
            cp_async16(base + 1 * KV_BYTES + so, ql_g + gk);
            cp_async16(base + 2 * KV_BYTES + so, qh_g + gv);
            cp_async16(base + 3 * KV_BYTES + so, ql_g + gv);
        }
        cp_commit();
    };
    issueKV(0, 0);       // commit groups Q + KV0
    issueKV(1, 64);
    cp_wait<1>(); __syncthreads();   // Q + KV0 ready

    // ---- preload Q fragments (m16k16 per k-step, hi & lo) ----
    uint32_t qh[4][4], ql[4][4];
    const int wq = warp * 16;
    #pragma unroll
    for (int ks = 0; ks < 4; ks++) {
        uint32_t off = (uint32_t)((wq + (lane & 15)) * ALDP + ks * 16 + (lane >> 4) * 8) * 2;
        ldm_x4(qh[ks][0], qh[ks][1], qh[ks][2], qh[ks][3], QHI + off);
        ldm_x4(ql[ks][0], ql[ks][1], ql[ks][2], ql[ks][3], QLO + off);
    }

    float o[8][4] = {};
    float mrow[2] = { -1e30f, -1e30f };
    float lrow[2] = {};
    const int NT = NSEQ / 64;

    for (int kt = 0; kt < NT; kt++) {
        if (kt > 0) {
            if (kt < NT - 1) cp_wait<1>(); else cp_wait<0>();
            __syncthreads();
        }
        uint32_t KB  = sb + 2 * QS_BYTES + (uint32_t)(kt & 1) * 4 * KV_BYTES;
        uint32_t KHI = KB, KLO = KB + KV_BYTES;
        uint32_t VHI = KB + 2 * KV_BYTES, VLO = KB + 3 * KV_BYTES;

        // ---- S = Q K^T (3-term split) ----
        float s[8][4] = {};
        #pragma unroll
        for (int j = 0; j < 8; j++) {
            uint32_t kbh[8], kbl[8];
            uint32_t a0 = (uint32_t)((j * 8 + (lane & 7)) * ALDP + (lane >> 3) * 8) * 2;
            ldm_x4(kbh[0], kbh[1], kbh[2], kbh[3], KHI + a0);          // ks0, ks1
            ldm_x4(kbh[4], kbh[5], kbh[6], kbh[7], KHI + a0 + 64);     // ks2, ks3 (+32 elems)
            ldm_x4(kbl[0], kbl[1], kbl[2], kbl[3], KLO + a0);
            ldm_x4(kbl[4], kbl[5], kbl[6], kbl[7], KLO + a0 + 64);
            #pragma unroll
            for (int ks = 0; ks < 4; ks++) {
                mma16816(s[j], qh[ks][0], qh[ks][1], qh[ks][2], qh[ks][3],
                         kbh[ks * 2], kbh[ks * 2 + 1]);
                mma16816(s[j], qh[ks][0], qh[ks][1], qh[ks][2], qh[ks][3],
                         kbl[ks * 2], kbl[ks * 2 + 1]);
                mma16816(s[j], ql[ks][0], ql[ks][1], ql[ks][2], ql[ks][3],
                         kbh[ks * 2], kbh[ks * 2 + 1]);
            }
        }

        // ---- online softmax (rows r0 = lane>>2, r1 = r0+8) ----
        float mx0 = -1e30f, mx1 = -1e30f;
        #pragma unroll
        for (int j = 0; j < 8; j++) {
            #pragma unroll
            for (int c = 0; c < 4; c++) s[j][c] *= 0.125f;
            mx0 = fmaxf(mx0, fmaxf(s[j][0], s[j][1]));
            mx1 = fmaxf(mx1, fmaxf(s[j][2], s[j][3]));
        }
        mx0 = fmaxf(mx0, __shfl_xor_sync(0xffffffffu, mx0, 1));
        mx0 = fmaxf(mx0, __shfl_xor_sync(0xffffffffu, mx0, 2));
        mx1 = fmaxf(mx1, __shfl_xor_sync(0xffffffffu, mx1, 1));
        mx1 = fmaxf(mx1, __shfl_xor_sync(0xffffffffu, mx1, 2));
        float mn0 = fmaxf(mrow[0], mx0), mn1 = fmaxf(mrow[1], mx1);
        float al0 = __expf(mrow[0] - mn0), al1 = __expf(mrow[1] - mn1);
        float rs0 = 0.f, rs1 = 0.f;
        #pragma unroll
        for (int j = 0; j < 8; j++) {
            s[j][0] = __expf(s[j][0] - mn0);
            s[j][1] = __expf(s[j][1] - mn0);
            s[j][2] = __expf(s[j][2] - mn1);
            s[j][3] = __expf(s[j][3] - mn1);
            rs0 += s[j][0] + s[j][1];
            rs1 += s[j][2] + s[j][3];
        }
        rs0 += __shfl_xor_sync(0xffffffffu, rs0, 1);
        rs0 += __shfl_xor_sync(0xffffffffu, rs0, 2);
        rs1 += __shfl_xor_sync(0xffffffffu, rs1, 1);
        rs1 += __shfl_xor_sync(0xffffffffu, rs1, 2);
        lrow[0] = lrow[0] * al0 + rs0;
        lrow[1] = lrow[1] * al1 + rs1;
        mrow[0] = mn0; mrow[1] = mn1;
        #pragma unroll
        for (int j = 0; j < 8; j++) {
            o[j][0] *= al0; o[j][1] *= al0;
            o[j][2] *= al1; o[j][3] *= al1;
        }

        // ---- pack P into A-fragments (hi + lo) ----
        uint32_t ph[4][4], pl[4][4];
        #pragma unroll
        for (int ks = 0; ks < 4; ks++) {
            split_pack2(s[2*ks][0],   s[2*ks][1],   ph[ks][0], pl[ks][0]);
            split_pack2(s[2*ks][2],   s[2*ks][3],   ph[ks][1], pl[ks][1]);
            split_pack2(s[2*ks+1][0], s[2*ks+1][1], ph[ks][2], pl[ks][2]);
            split_pack2(s[2*ks+1][2], s[2*ks+1][3], ph[ks][3], pl[ks][3]);
        }

        // ---- O += P V (3-term split), V via ldmatrix.trans ----
        #pragma unroll
        for (int ks = 0; ks < 4; ks++) {
            #pragma unroll
            for (int jp = 0; jp < 4; jp++) {
                uint32_t vh[4], vl[4];
                uint32_t addr = (uint32_t)(
                    (ks * 16 + (lane & 7) + ((lane >> 3) & 1) * 8) * ALDP +
                    jp * 16 + (lane >> 4) * 8) * 2;
                ldm_x4_t(vh[0], vh[1], vh[2], vh[3], VHI + addr);
                ldm_x4_t(vl[0], vl[1], vl[2], vl[3], VLO + addr);
                mma16816(o[jp*2],   ph[ks][0], ph[ks][1], ph[ks][2], ph[ks][3], vh[0], vh[1]);
                mma16816(o[jp*2],   ph[ks][0], ph[ks][1], ph[ks][2], ph[ks][3], vl[0], vl[1]);
                mma16816(o[jp*2],   pl[ks][0], pl[ks][1], pl[ks][2], pl[ks][3], vh[0], vh[1]);
                mma16816(o[jp*2+1], ph[ks][0], ph[ks][1], ph[ks][2], ph[ks][3], vh[2], vh[3]);
                mma16816(o[jp*2+1], ph[ks][0], ph[ks][1], ph[ks][2], ph[ks][3], vl[2], vl[3]);
                mma16816(o[jp*2+1], pl[ks][0], pl[ks][1], pl[ks][2], pl[ks][3], vh[2], vh[3]);
            }
        }

        __syncthreads();
        if (kt + 2 < NT) issueKV(kt & 1, (kt + 2) * 64);
    }

    // ---- epilogue: normalize, split, store ----
    float inv0 = 1.0f / lrow[0], inv1 = 1.0f / lrow[1];
    int r0 = q0 + wq + (lane >> 2);
    #pragma unroll
    for (int j = 0; j < 8; j++) {
        int col = hh * 64 + j * 8 + (lane & 3) * 2;
        size_t off0 = (size_t)(b * NSEQ + r0) * CDIM + col;
        size_t off1 = (size_t)(b * NSEQ + r0 + 8) * CDIM + col;
        uint32_t h01, l01, h23, l23;
        split_pack2(o[j][0] * inv0, o[j][1] * inv0, h01, l01);
        split_pack2(o[j][2] * inv1, o[j][3] * inv1, h23, l23);
        *(uint32_t*)(ohi + off0) = h01;
        *(uint32_t*)(ohi + off1) = h23;
        *(uint32_t*)(olo + off0) = l01;
        *(uint32_t*)(olo + off1) = l23;
    }
}

// -------------------- launch --------------------
extern "C" void kernel_launch(void* const* d_in, const int* in_sizes, int n_in,
                              void* d_out, int out_size) {
    const float* x      = (const float*)d_in[0];
    const float* qkv_w  = (const float*)d_in[1];
    const float* proj_w = (const float*)d_in[2];
    const float* proj_b = (const float*)d_in[3];
    const float* n1w    = (const float*)d_in[4];
    const float* n1b    = (const float*)d_in[5];
    const float* n2w    = (const float*)d_in[6];
    const float* n2b    = (const float*)d_in[7];
    const float* fc1w   = (const float*)d_in[8];
    const float* fc1b   = (const float*)d_in[9];
    const float* fc2w   = (const float*)d_in[10];
    const float* fc2b   = (const float*)d_in[11];
    float* out = (float*)d_out;

    static bool s_init = false;
    static __nv_bfloat16 *xhi, *xlo, *qh, *ql, *ahi, *alo, *mhi, *mlo;
    static __nv_bfloat16 *wqh, *wql, *wph, *wpl, *w1h, *w1l, *w2h, *w2l;
    static float *x1;
    if (!s_init) {
        cudaGetSymbolAddress((void**)&xhi, g_xhi);
        cudaGetSymbolAddress((void**)&xlo, g_xlo);
        cudaGetSymbolAddress((void**)&qh,  g_qkvh);
        cudaGetSymbolAddress((void**)&ql,  g_qkvl);
        cudaGetSymbolAddress((void**)&ahi, g_ahi);
        cudaGetSymbolAddress((void**)&alo, g_alo);
        cudaGetSymbolAddress((void**)&x1,  g_x1);
        cudaGetSymbolAddress((void**)&mhi, g_mhi);
        cudaGetSymbolAddress((void**)&mlo, g_mlo);
        cudaGetSymbolAddress((void**)&wqh, g_wqkvh);
        cudaGetSymbolAddress((void**)&wql, g_wqkvl);
        cudaGetSymbolAddress((void**)&wph, g_wprjh);
        cudaGetSymbolAddress((void**)&wpl, g_wprjl);
        cudaGetSymbolAddress((void**)&w1h, g_wf1h);
        cudaGetSymbolAddress((void**)&w1l, g_wf1l);
        cudaGetSymbolAddress((void**)&w2h, g_wf2h);
        cudaGetSymbolAddress((void**)&w2l, g_wf2l);
        cudaFuncSetAttribute(attn_tc,
                             cudaFuncAttributeMaxDynamicSharedMemorySize, ATTN_SMEM);
        cudaFuncSetAttribute(gemm_tc<0,1>,
                             cudaFuncAttributeMaxDynamicSharedMemorySize, GSMEM);
        cudaFuncSetAttribute(gemm_tc<2,0>,
                             cudaFuncAttributeMaxDynamicSharedMemorySize, GSMEM);
        cudaFuncSetAttribute(gemm_tc<3,1>,
                             cudaFuncAttributeMaxDynamicSharedMemorySize, GSMEM);
        s_init = true;
    }
    (void)in_sizes; (void)n_in; (void)out_size;

    dim3 thr(256);

    // weight splits
    wconv_kernel<<<(H3*CDIM/4 + 255)/256, thr>>>(qkv_w,  wqh, wql, H3*CDIM/4);
    wconv_kernel<<<(CDIM*CDIM/4 + 255)/256, thr>>>(proj_w, wph, wpl, CDIM*CDIM/4);
    wconv_kernel<<<(HID*CDIM/4 + 255)/256, thr>>>(fc1w,  w1h, w1l, HID*CDIM/4);
    wconv_kernel<<<(CDIM*HID/4 + 255)/256, thr>>>(fc2w,  w2h, w2l, CDIM*HID/4);

    // 1. LN1 -> hi/lo
    ln_kernel<<<MDIM, thr>>>(x, n1w, n1b, xhi, xlo);
    // 2. qkv = h @ qkv_w^T  -> bf16 hi/lo
    gemm_tc<0,1><<<dim3(H3/128, MDIM/128), thr, GSMEM>>>(
        xhi, xlo, wqh, wql, nullptr, nullptr, nullptr, qh, ql, H3, CDIM);
    // 3. attention (tensor core) -> hi/lo
    attn_tc<<<dim3(NSEQ/128, BATCH*NHEADS), thr, ATTN_SMEM>>>(qh, ql, ahi, alo);
    // 4. x1 = x + attn @ proj_w^T + proj_b
    gemm_tc<2,0><<<dim3(CDIM/128, MDIM/128), thr, GSMEM>>>(
        ahi, alo, wph, wpl, proj_b, x, x1, nullptr, nullptr, CDIM, CDIM);
    // 5. LN2 -> hi/lo
    ln_kernel<<<MDIM, thr>>>(x1, n2w, n2b, xhi, xlo);
    // 6. mlp = gelu(h2 @ fc1_w^T + fc1_b) -> hi/lo
    gemm_tc<3,1><<<dim3(HID/128, MDIM/128), thr, GSMEM>>>(
        xhi, xlo, w1h, w1l, fc1b, nullptr, nullptr, mhi, mlo, HID, CDIM);
    // 7. out = x1 + mlp @ fc2_w^T + fc2_b
    gemm_tc<2,0><<<dim3(CDIM/128, MDIM/128), thr, GSMEM>>>(
        mhi, mlo, w2h, w2l, fc2b, x1, out, nullptr, nullptr, CDIM, HID);
}

// round 14
// speedup vs baseline: 4.3284x; 1.3093x over previous
#include <cuda_runtime.h>
#include <cuda_fp16.h>
#include <math.h>
#include <stdint.h>

// Problem constants
#define BATCH   4
#define NSEQ    2048
#define CDIM    768
#define NHEADS  12
#define H3      2304      // 3*CDIM
#define HID     3072      // 4*CDIM
#define MDIM    (BATCH*NSEQ)   // 8192 rows

// -------------------- scratch (no allocations allowed) --------------------
__device__ __half g_xhi[MDIM * CDIM], g_xlo[MDIM * CDIM];  // LN out
__device__ __half g_qkvh[MDIM * H3],  g_qkvl[MDIM * H3];   // qkv hi/lo
__device__ __half g_ahi[MDIM * CDIM], g_alo[MDIM * CDIM];  // attn out
__device__ float  g_x1 [MDIM * CDIM];                      // residual 1
__device__ __half g_mhi[MDIM * HID],  g_mlo[MDIM * HID];   // mlp (post-gelu)
__device__ __half g_wqkv[H3 * CDIM];
__device__ __half g_wprj[CDIM * CDIM];
__device__ __half g_wf1 [HID * CDIM];
__device__ __half g_wf2 [CDIM * HID];

// -------------------- small helpers --------------------
__device__ __forceinline__ void split2(float x, __half& hi, __half& lo) {
    hi = __float2half_rn(x);
    lo = __float2half_rn(x - __half2float(hi));
}
__device__ __forceinline__ void split_pack2(float x, float y, uint32_t& hi, uint32_t& lo) {
    __half hx, lx, hy, ly;
    split2(x, hx, lx); split2(y, hy, ly);
    __half2 H(hx, hy), L(lx, ly);
    hi = *(uint32_t*)&H; lo = *(uint32_t*)&L;
}
__device__ __forceinline__ void cp_async16(uint32_t dst, const void* src) {
    asm volatile("cp.async.cg.shared.global [%0], [%1], 16;\n" :: "r"(dst), "l"(src));
}
__device__ __forceinline__ void cp_commit() {
    asm volatile("cp.async.commit_group;\n");
}
template<int N> __device__ __forceinline__ void cp_wait() {
    asm volatile("cp.async.wait_group %0;\n" :: "n"(N));
}
__device__ __forceinline__ void ldm_x4(uint32_t& r0, uint32_t& r1, uint32_t& r2, uint32_t& r3,
                                       uint32_t addr) {
    asm volatile("ldmatrix.sync.aligned.m8n8.x4.shared.b16 {%0,%1,%2,%3},[%4];\n"
                 : "=r"(r0), "=r"(r1), "=r"(r2), "=r"(r3) : "r"(addr));
}
__device__ __forceinline__ void ldm_x4_t(uint32_t& r0, uint32_t& r1, uint32_t& r2, uint32_t& r3,
                                         uint32_t addr) {
    asm volatile("ldmatrix.sync.aligned.m8n8.x4.trans.shared.b16 {%0,%1,%2,%3},[%4];\n"
                 : "=r"(r0), "=r"(r1), "=r"(r2), "=r"(r3) : "r"(addr));
}
__device__ __forceinline__ void ldm_x2(uint32_t& r0, uint32_t& r1, uint32_t addr) {
    asm volatile("ldmatrix.sync.aligned.m8n8.x2.shared.b16 {%0,%1},[%2];\n"
                 : "=r"(r0), "=r"(r1) : "r"(addr));
}
__device__ __forceinline__ void mma16816(float* c, uint32_t a0, uint32_t a1, uint32_t a2,
                                         uint32_t a3, uint32_t b0, uint32_t b1) {
    asm volatile("mma.sync.aligned.m16n8k16.row.col.f32.f16.f16.f32 "
                 "{%0,%1,%2,%3},{%4,%5,%6,%7},{%8,%9},{%0,%1,%2,%3};\n"
                 : "+f"(c[0]), "+f"(c[1]), "+f"(c[2]), "+f"(c[3])
                 : "r"(a0), "r"(a1), "r"(a2), "r"(a3), "r"(b0), "r"(b1));
}

// -------------------- weight convert: fp32 -> fp16 (single) --------------------
__global__ __launch_bounds__(256)
void wconv_kernel(const float* __restrict__ w,
                  __half* __restrict__ hi, int n4) {
    int i = blockIdx.x * blockDim.x + threadIdx.x;
    if (i >= n4) return;
    float4 v = ((const float4*)w)[i];
    __half2 a(__float2half_rn(v.x), __float2half_rn(v.y));
    __half2 b(__float2half_rn(v.z), __float2half_rn(v.w));
    ((__half2*)hi)[i * 2]     = a;
    ((__half2*)hi)[i * 2 + 1] = b;
}

// -------------------- LayerNorm -> fp16 hi/lo --------------------
__global__ __launch_bounds__(256)
void ln_kernel(const float* __restrict__ x,
               const float* __restrict__ w,
               const float* __restrict__ b,
               __half* __restrict__ yhi,
               __half* __restrict__ ylo) {
    int row = blockIdx.x;
    const float* xr = x + (size_t)row * CDIM;
    int t = threadIdx.x;
    float v0 = xr[t], v1 = xr[t + 256], v2 = xr[t + 512];
    float s  = v0 + v1 + v2;
    float ss = v0*v0 + v1*v1 + v2*v2;
    #pragma unroll
    for (int o = 16; o > 0; o >>= 1) {
        s  += __shfl_xor_sync(0xffffffffu, s,  o);
        ss += __shfl_xor_sync(0xffffffffu, ss, o);
    }
    __shared__ float sh_s[8], sh_ss[8];
    __shared__ float sh_mean, sh_rstd;
    int warp = t >> 5, lane = t & 31;
    if (lane == 0) { sh_s[warp] = s; sh_ss[warp] = ss; }
    __syncthreads();
    if (t == 0) {
        float ts = 0.f, tss = 0.f;
        #pragma unroll
        for (int i = 0; i < 8; i++) { ts += sh_s[i]; tss += sh_ss[i]; }
        float mean = ts * (1.0f / CDIM);
        float var  = tss * (1.0f / CDIM) - mean * mean;
        sh_mean = mean;
        sh_rstd = rsqrtf(var + 1e-5f);
    }
    __syncthreads();
    float mean = sh_mean, r = sh_rstd;
    size_t base = (size_t)row * CDIM;
    #pragma unroll
    for (int p = 0; p < 3; p++) {
        int c = t + p * 256;
        float v = (p == 0) ? v0 : (p == 1) ? v1 : v2;
        float y = (v - mean) * r * w[c] + b[c];
        __half hi, lo;
        split2(y, hi, lo);
        yhi[base + c] = hi;
        ylo[base + c] = lo;
    }
}

// ========== tensor-core GEMM: Y[M,N] = X[M,K] @ W[N,K]^T ==========
// A = activations (2-term fp16 split: Ahi+Alo exact), B = weights (single fp16).
// 2 mma per fragment pair: AhB + AlB.
// EPI: 0 = none, 2 = +bias+residual, 3 = +bias+gelu    OUT: 0 = fp32, 1 = fp16 hi/lo
#define LDP   40                 // padded row stride (fp16 elems)
#define TILE  (128 * LDP)        // one operand tile in smem (elems)
#define STAGE (3 * TILE)         // Ahi, Alo, B
#define GSMEM (2 * STAGE * 2)    // bytes (2 stages) = 61440

template<int EPI, int OUT>
__global__ __launch_bounds__(256)
void gemm_tc(const __half* __restrict__ Ahi, const __half* __restrict__ Alo,
             const __half* __restrict__ B,
             const float* __restrict__ bias, const float* __restrict__ res,
             float* __restrict__ Y,
             __half* __restrict__ Yhi, __half* __restrict__ Ylo,
             int Nout, int K) {
    extern __shared__ __align__(16) char smem_raw[];
    uint32_t sbase = (uint32_t)__cvta_generic_to_shared(smem_raw);

    const int t = threadIdx.x, lane = t & 31, warp = t >> 5;
    const int wm = (warp & 1) * 64;    // warp m-offset in tile
    const int wn = (warp >> 1) * 32;   // warp n-offset in tile
    const int m0 = blockIdx.y * 128, n0 = blockIdx.x * 128;

    float acc[4][4][4] = {};   // [m-frag][n-frag][c0..c3]

    auto issue = [&](int s, int k0) {
        uint32_t so = sbase + (uint32_t)(s * STAGE) * 2;
        #pragma unroll
        for (int p = 0; p < 2; p++) {
            int idx = t + p * 256;          // 0..511
            int row = idx >> 2;
            int c8  = (idx & 3) * 8;        // fp16 col offset
            size_t ga = (size_t)(m0 + row) * K + k0 + c8;
            size_t gb = (size_t)(n0 + row) * K + k0 + c8;
            uint32_t sm = (uint32_t)(row * LDP + c8) * 2;
            cp_async16(so + 0 * TILE * 2 + sm, Ahi + ga);
            cp_async16(so + 1 * TILE * 2 + sm, Alo + ga);
            cp_async16(so + 2 * TILE * 2 + sm, B + gb);
        }
        cp_commit();
    };

    issue(0, 0);
    const int KT = K / 32;
    for (int kt = 0; kt < KT; kt++) {
        if (kt + 1 < KT) { issue((kt + 1) & 1, (kt + 1) * 32); cp_wait<1>(); }
        else             { cp_wait<0>(); }
        __syncthreads();

        uint32_t so = sbase + (uint32_t)((kt & 1) * STAGE) * 2;
        #pragma unroll
        for (int ks = 0; ks < 2; ks++) {
            uint32_t ahi[4][4], alo[4][4];
            #pragma unroll
            for (int i = 0; i < 4; i++) {
                uint32_t off = (uint32_t)((wm + i * 16 + (lane & 15)) * LDP +
                                          ks * 16 + (lane >> 4) * 8) * 2;
                ldm_x4(ahi[i][0], ahi[i][1], ahi[i][2], ahi[i][3], so + 0 * TILE * 2 + off);
                ldm_x4(alo[i][0], alo[i][1], alo[i][2], alo[i][3], so + 1 * TILE * 2 + off);
            }
            uint32_t bh[4][2];
            #pragma unroll
            for (int j = 0; j < 4; j++) {
                int q = lane & 15;
                uint32_t off = (uint32_t)((wn + j * 8 + (q & 7)) * LDP +
                                          ks * 16 + (q >> 3) * 8) * 2;
                ldm_x2(bh[j][0], bh[j][1], so + 2 * TILE * 2 + off);
            }
            #pragma unroll
            for (int i = 0; i < 4; i++)
                #pragma unroll
                for (int j = 0; j < 4; j++) {
                    mma16816(acc[i][j], ahi[i][0], ahi[i][1], ahi[i][2], ahi[i][3],
                             bh[j][0], bh[j][1]);
                    mma16816(acc[i][j], alo[i][0], alo[i][1], alo[i][2], alo[i][3],
                             bh[j][0], bh[j][1]);
                }
        }
        __syncthreads();
    }

    // ---- epilogue ----
    const int g = lane >> 2, tig = lane & 3;
    #pragma unroll
    for (int i = 0; i < 4; i++) {
        int rowa = m0 + wm + i * 16 + g;
        #pragma unroll
        for (int j = 0; j < 4; j++) {
            int coln = n0 + wn + j * 8 + tig * 2;
            float v[4] = { acc[i][j][0], acc[i][j][1], acc[i][j][2], acc[i][j][3] };
            if (EPI >= 2) {
                float b0 = bias[coln], b1 = bias[coln + 1];
                v[0] += b0; v[1] += b1; v[2] += b0; v[3] += b1;
            }
            size_t off0 = (size_t)rowa * Nout + coln;
            size_t off1 = (size_t)(rowa + 8) * Nout + coln;
            if (EPI == 2) {
                float2 r0 = *(const float2*)(res + off0);
                float2 r1 = *(const float2*)(res + off1);
                v[0] += r0.x; v[1] += r0.y; v[2] += r1.x; v[3] += r1.y;
            }
            if (EPI == 3) {
                #pragma unroll
                for (int e = 0; e < 4; e++)
                    v[e] = 0.5f * v[e] * (1.0f + erff(v[e] * 0.70710678118654752f));
            }
            if (OUT == 0) {
                *(float2*)(Y + off0) = make_float2(v[0], v[1]);
                *(float2*)(Y + off1) = make_float2(v[2], v[3]);
            } else {
                uint32_t h01, l01, h23, l23;
                split_pack2(v[0], v[1], h01, l01);
                split_pack2(v[2], v[3], h23, l23);
                *(uint32_t*)(Yhi + off0) = h01;
                *(uint32_t*)(Yhi + off1) = h23;
                *(uint32_t*)(Ylo + off0) = l01;
                *(uint32_t*)(Ylo + off1) = l23;
            }
        }
    }
}

// ========== tensor-core flash attention (fp16 splits) ==========
// S = QK^T: 3-term (Q 2-term x K 2-term, drop lo*lo) — logit precision.
// PV: 2-term (P 2-term x V hi) — V rounding 2^-11 is benign.
// CTA: 128 q-rows, 8 warps, 64-key tiles, 2-stage K/V pipeline.
#define ALDP 72                         // padded row (64 d + 8)
#define QS_BYTES  (128 * ALDP * 2)      // one Q array
#define KV_BYTES  (64 * ALDP * 2)       // one K or V array
#define ATTN_SMEM (2 * QS_BYTES + 2 * 3 * KV_BYTES)   // 92160 B

__global__ __launch_bounds__(256)
void attn_tc(const __half* __restrict__ qh_g,
             const __half* __restrict__ ql_g,
             __half* __restrict__ ohi,
             __half* __restrict__ olo) {
    extern __shared__ __align__(16) char smem_raw2[];
    uint32_t sb = (uint32_t)__cvta_generic_to_shared(smem_raw2);
    const int t = threadIdx.x, lane = t & 31, warp = t >> 5;
    const int bidx = blockIdx.y;
    const int b = bidx / NHEADS, hh = bidx % NHEADS;
    const int q0 = blockIdx.x * 128;
    const uint32_t QHI = sb, QLO = sb + QS_BYTES;

    #pragma unroll
    for (int p = 0; p < 4; p++) {
        int idx = t + p * 256;          // 0..1023
        int row = idx >> 3, ch = idx & 7;
        size_t g = (size_t)(b * NSEQ + q0 + row) * H3 + hh * 64 + ch * 8;
        uint32_t so = (uint32_t)(row * ALDP + ch * 8) * 2;
        cp_async16(QHI + so, qh_g + g);
        cp_async16(QLO + so, ql_g + g);
    }
    auto issueKV = [&](int s, int j0) {
        uint32_t base = sb + 2 * QS_BYTES + (uint32_t)s * 3 * KV_BYTES;
        #pragma unroll
        for (int p = 0; p < 2; p++) {
            int idx = t + p * 256;      // 0..511
            int row = idx >> 3, ch = idx & 7;
            size_t gk = (size_t)(b * NSEQ + j0 + row) * H3 + CDIM + hh * 64 + ch * 8;
            size_t gv = gk + CDIM;
            uint32_t so = (uint32_t)(row * ALDP + ch * 8) * 2;
            cp_async16(base + 0 * KV_BYTES + so, qh_g + gk);   // K hi
            cp_async16(base + 1 * KV_BYTES + so, ql_g + gk);   // K lo
            cp_async16(base + 2 * KV_BYTES + so, qh_g + gv);   // V hi
        }
        cp_commit();
    };
    issueKV(0, 0);
    issueKV(1, 64);
    cp_wait<1>(); __syncthreads();

    uint32_t qh[4][4], ql[4][4];
    const int wq = warp * 16;
    #pragma unroll
    for (int ks = 0; ks < 4; ks++) {
        uint32_t off = (uint32_t)((wq + (lane & 15)) * ALDP + ks * 16 + (lane >> 4) * 8) * 2;
        ldm_x4(qh[ks][0], qh[ks][1], qh[ks][2], qh[ks][3], QHI + off);
        ldm_x4(ql[ks][0], ql[ks][1], ql[ks][2], ql[ks][3], QLO + off);
    }

    float o[8][4] = {};
    float mrow[2] = { -1e30f, -1e30f };
    float lrow[2] = {};
    const int NT = NSEQ / 64;

    for (int kt = 0; kt < NT; kt++) {
        if (kt > 0) {
            if (kt < NT - 1) cp_wait<1>(); else cp_wait<0>();
            __syncthreads();
        }
        uint32_t KB  = sb + 2 * QS_BYTES + (uint32_t)(kt & 1) * 3 * KV_BYTES;
        uint32_t KHI = KB, KLO = KB + KV_BYTES;
        uint32_t VHI = KB + 2 * KV_BYTES;

        // ---- S = Q K^T (3-term) ----
        float s[8][4] = {};
        #pragma unroll
        for (int j = 0; j < 8; j++) {
            uint32_t kbh[8], kbl[8];
            uint32_t a0 = (uint32_t)((j * 8 + (lane & 7)) * ALDP + (lane >> 3) * 8) * 2;
            ldm_x4(kbh[0], kbh[1], kbh[2], kbh[3], KHI + a0);
            ldm_x4(kbh[4], kbh[5], kbh[6], kbh[7], KHI + a0 + 64);
            ldm_x4(kbl[0], kbl[1], kbl[2], kbl[3], KLO + a0);
            ldm_x4(kbl[4], kbl[5], kbl[6], kbl[7], KLO + a0 + 64);
            #pragma unroll
            for (int ks = 0; ks < 4; ks++) {
                mma16816(s[j], qh[ks][0], qh[ks][1], qh[ks][2], qh[ks][3],
                         kbh[ks * 2], kbh[ks * 2 + 1]);
                mma16816(s[j], qh[ks][0], qh[ks][1], qh[ks][2], qh[ks][3],
                         kbl[ks * 2], kbl[ks * 2 + 1]);
                mma16816(s[j], ql[ks][0], ql[ks][1], ql[ks][2], ql[ks][3],
                         kbh[ks * 2], kbh[ks * 2 + 1]);
            }
        }

        // ---- online softmax ----
        float mx0 = -1e30f, mx1 = -1e30f;
        #pragma unroll
        for (int j = 0; j < 8; j++) {
            #pragma unroll
            for (int c = 0; c < 4; c++) s[j][c] *= 0.125f;
            mx0 = fmaxf(mx0, fmaxf(s[j][0], s[j][1]));
            mx1 = fmaxf(mx1, fmaxf(s[j][2], s[j][3]));
        }
        mx0 = fmaxf(mx0, __shfl_xor_sync(0xffffffffu, mx0, 1));
        mx0 = fmaxf(mx0, __shfl_xor_sync(0xffffffffu, mx0, 2));
        mx1 = fmaxf(mx1, __shfl_xor_sync(0xffffffffu, mx1, 1));
        mx1 = fmaxf(mx1, __shfl_xor_sync(0xffffffffu, mx1, 2));
        float mn0 = fmaxf(mrow[0], mx0), mn1 = fmaxf(mrow[1], mx1);
        float al0 = __expf(mrow[0] - mn0), al1 = __expf(mrow[1] - mn1);
        float rs0 = 0.f, rs1 = 0.f;
        #pragma unroll
        for (int j = 0; j < 8; j++) {
            s[j][0] = __expf(s[j][0] - mn0);
            s[j][1] = __expf(s[j][1] - mn0);
            s[j][2] = __expf(s[j][2] - mn1);
            s[j][3] = __expf(s[j][3] - mn1);
            rs0 += s[j][0] + s[j][1];
            rs1 += s[j][2] + s[j][3];
        }
        rs0 += __shfl_xor_sync(0xffffffffu, rs0, 1);
        rs0 += __shfl_xor_sync(0xffffffffu, rs0, 2);
        rs1 += __shfl_xor_sync(0xffffffffu, rs1, 1);
        rs1 += __shfl_xor_sync(0xffffffffu, rs1, 2);
        lrow[0] = lrow[0] * al0 + rs0;
        lrow[1] = lrow[1] * al1 + rs1;
        mrow[0] = mn0; mrow[1] = mn1;
        #pragma unroll
        for (int j = 0; j < 8; j++) {
            o[j][0] *= al0; o[j][1] *= al0;
            o[j][2] *= al1; o[j][3] *= al1;
        }

        // ---- pack P into A-fragments (hi + lo) ----
        uint32_t ph[4][4], pl[4][4];
        #pragma unroll
        for (int ks = 0; ks < 4; ks++) {
            split_pack2(s[2*ks][0],   s[2*ks][1],   ph[ks][0], pl[ks][0]);
            split_pack2(s[2*ks][2],   s[2*ks][3],   ph[ks][1], pl[ks][1]);
            split_pack2(s[2*ks+1][0], s[2*ks+1][1], ph[ks][2], pl[ks][2]);
            split_pack2(s[2*ks+1][2], s[2*ks+1][3], ph[ks][3], pl[ks][3]);
        }

        // ---- O += P V (2-term: PhVh + PlVh), V via ldmatrix.trans ----
        #pragma unroll
        for (int ks = 0; ks < 4; ks++) {
            #pragma unroll
            for (int jp = 0; jp < 4; jp++) {
                uint32_t vh[4];
                uint32_t addr = (uint32_t)(
                    (ks * 16 + (lane & 7) + ((lane >> 3) & 1) * 8) * ALDP +
                    jp * 16 + (lane >> 4) * 8) * 2;
                ldm_x4_t(vh[0], vh[1], vh[2], vh[3], VHI + addr);
                mma16816(o[jp*2],   ph[ks][0], ph[ks][1], ph[ks][2], ph[ks][3], vh[0], vh[1]);
                mma16816(o[jp*2],   pl[ks][0], pl[ks][1], pl[ks][2], pl[ks][3], vh[0], vh[1]);
                mma16816(o[jp*2+1], ph[ks][0], ph[ks][1], ph[ks][2], ph[ks][3], vh[2], vh[3]);
                mma16816(o[jp*2+1], pl[ks][0], pl[ks][1], pl[ks][2], pl[ks][3], vh[2], vh[3]);
            }
        }

        __syncthreads();
        if (kt + 2 < NT) issueKV(kt & 1, (kt + 2) * 64);
    }

    // ---- epilogue: normalize, split, store ----
    float inv0 = 1.0f / lrow[0], inv1 = 1.0f / lrow[1];
    int r0 = q0 + wq + (lane >> 2);
    #pragma unroll
    for (int j = 0; j < 8; j++) {
        int col = hh * 64 + j * 8 + (lane & 3) * 2;
        size_t off0 = (size_t)(b * NSEQ + r0) * CDIM + col;
        size_t off1 = (size_t)(b * NSEQ + r0 + 8) * CDIM + col;
        uint32_t h01, l01, h23, l23;
        split_pack2(o[j][0] * inv0, o[j][1] * inv0, h01, l01);
        split_pack2(o[j][2] * inv1, o[j][3] * inv1, h23, l23);
        *(uint32_t*)(ohi + off0) = h01;
        *(uint32_t*)(ohi + off1) = h23;
        *(uint32_t*)(olo + off0) = l01;
        *(uint32_t*)(olo + off1) = l23;
    }
}

// -------------------- launch --------------------
extern "C" void kernel_launch(void* const* d_in, const int* in_sizes, int n_in,
                              void* d_out, int out_size) {
    const float* x      = (const float*)d_in[0];
    const float* qkv_w  = (const float*)d_in[1];
    const float* proj_w = (const float*)d_in[2];
    const float* proj_b = (const float*)d_in[3];
    const float* n1w    = (const float*)d_in[4];
    const float* n1b    = (const float*)d_in[5];
    const float* n2w    = (const float*)d_in[6];
    const float* n2b    = (const float*)d_in[7];
    const float* fc1w   = (const float*)d_in[8];
    const float* fc1b   = (const float*)d_in[9];
    const float* fc2w   = (const float*)d_in[10];
    const float* fc2b   = (const float*)d_in[11];
    float* out = (float*)d_out;

    static bool s_init = false;
    static __half *xhi, *xlo, *qh, *ql, *ahi, *alo, *mhi, *mlo;
    static __half *wq, *wp, *w1, *w2;
    static float *x1;
    if (!s_init) {
        cudaGetSymbolAddress((void**)&xhi, g_xhi);
        cudaGetSymbolAddress((void**)&xlo, g_xlo);
        cudaGetSymbolAddress((void**)&qh,  g_qkvh);
        cudaGetSymbolAddress((void**)&ql,  g_qkvl);
        cudaGetSymbolAddress((void**)&ahi, g_ahi);
        cudaGetSymbolAddress((void**)&alo, g_alo);
        cudaGetSymbolAddress((void**)&x1,  g_x1);
        cudaGetSymbolAddress((void**)&mhi, g_mhi);
        cudaGetSymbolAddress((void**)&mlo, g_mlo);
        cudaGetSymbolAddress((void**)&wq,  g_wqkv);
        cudaGetSymbolAddress((void**)&wp,  g_wprj);
        cudaGetSymbolAddress((void**)&w1,  g_wf1);
        cudaGetSymbolAddress((void**)&w2,  g_wf2);
        cudaFuncSetAttribute(attn_tc,
                             cudaFuncAttributeMaxDynamicSharedMemorySize, ATTN_SMEM);
        cudaFuncSetAttribute(gemm_tc<0,1>,
                             cudaFuncAttributeMaxDynamicSharedMemorySize, GSMEM);
        cudaFuncSetAttribute(gemm_tc<2,0>,
                             cudaFuncAttributeMaxDynamicSharedMemorySize, GSMEM);
        cudaFuncSetAttribute(gemm_tc<3,1>,
                             cudaFuncAttributeMaxDynamicSharedMemorySize, GSMEM);
        s_init = true;
    }
    (void)in_sizes; (void)n_in; (void)out_size;

    dim3 thr(256);

    // weight converts (fp32 -> fp16)
    wconv_kernel<<<(H3*CDIM/4 + 255)/256, thr>>>(qkv_w,  wq, H3*CDIM/4);
    wconv_kernel<<<(CDIM*CDIM/4 + 255)/256, thr>>>(proj_w, wp, CDIM*CDIM/4);
    wconv_kernel<<<(HID*CDIM/4 + 255)/256, thr>>>(fc1w,  w1, HID*CDIM/4);
    wconv_kernel<<<(CDIM*HID/4 + 255)/256, thr>>>(fc2w,  w2, CDIM*HID/4);

    // 1. LN1 -> hi/lo
    ln_kernel<<<MDIM, thr>>>(x, n1w, n1b, xhi, xlo);
    // 2. qkv = h @ qkv_w^T  -> fp16 hi/lo
    gemm_tc<0,1><<<dim3(H3/128, MDIM/128), thr, GSMEM>>>(
        xhi, xlo, wq, nullptr, nullptr, nullptr, qh, ql, H3, CDIM);
    // 3. attention (tensor core) -> hi/lo
    attn_tc<<<dim3(NSEQ/128, BATCH*NHEADS), thr, ATTN_SMEM>>>(qh, ql, ahi, alo);
    // 4. x1 = x + attn @ proj_w^T + proj_b
    gemm_tc<2,0><<<dim3(CDIM/128, MDIM/128), thr, GSMEM>>>(
        ahi, alo, wp, proj_b, x, x1, nullptr, nullptr, CDIM, CDIM);
    // 5. LN2 -> hi/lo
    ln_kernel<<<MDIM, thr>>>(x1, n2w, n2b, xhi, xlo);
    // 6. mlp = gelu(h2 @ fc1_w^T + fc1_b) -> hi/lo
    gemm_tc<3,1><<<dim3(HID/128, MDIM/128), thr, GSMEM>>>(
        xhi, xlo, w1, fc1b, nullptr, nullptr, mhi, mlo, HID, CDIM);
    // 7. out = x1 + mlp @ fc2_w^T + fc2_b
    gemm_tc<2,0><<<dim3(CDIM/128, MDIM/128), thr, GSMEM>>>(
        mhi, mlo, w2, fc2b, x1, out, nullptr, nullptr, CDIM, HID);
}

// round 15
// speedup vs baseline: 6.8303x; 1.5780x over previous
#include <cuda_runtime.h>
#include <cuda_fp16.h>
#include <math.h>
#include <stdint.h>

// Problem constants
#define BATCH   4
#define NSEQ    2048
#define CDIM    768
#define NHEADS  12
#define H3      2304      // 3*CDIM
#define HID     3072      // 4*CDIM
#define MDIM    (BATCH*NSEQ)   // 8192 rows

// -------------------- scratch (no allocations allowed) --------------------
__device__ __half g_xh [MDIM * CDIM];   // LN out (single fp16)
__device__ __half g_qkv[MDIM * H3];     // qkv (single fp16)
__device__ __half g_ah [MDIM * CDIM];   // attn out (single fp16)
__device__ float  g_x1 [MDIM * CDIM];   // residual 1 (fp32)
__device__ __half g_mh [MDIM * HID];    // mlp post-gelu (single fp16)
__device__ __half g_wqkv[H3 * CDIM];
__device__ __half g_wprj[CDIM * CDIM];
__device__ __half g_wf1 [HID * CDIM];
__device__ __half g_wf2 [CDIM * HID];

// -------------------- small helpers --------------------
__device__ __forceinline__ void split2(float x, __half& hi, __half& lo) {
    hi = __float2half_rn(x);
    lo = __float2half_rn(x - __half2float(hi));
}
__device__ __forceinline__ void split_pack2(float x, float y, uint32_t& hi, uint32_t& lo) {
    __half hx, lx, hy, ly;
    split2(x, hx, lx); split2(y, hy, ly);
    __half2 H(hx, hy), L(lx, ly);
    hi = *(uint32_t*)&H; lo = *(uint32_t*)&L;
}
__device__ __forceinline__ uint32_t pack_h2(float x, float y) {
    __half2 H(__float2half_rn(x), __float2half_rn(y));
    return *(uint32_t*)&H;
}
__device__ __forceinline__ void cp_async16(uint32_t dst, const void* src) {
    asm volatile("cp.async.cg.shared.global [%0], [%1], 16;\n" :: "r"(dst), "l"(src));
}
__device__ __forceinline__ void cp_commit() {
    asm volatile("cp.async.commit_group;\n");
}
template<int N> __device__ __forceinline__ void cp_wait() {
    asm volatile("cp.async.wait_group %0;\n" :: "n"(N));
}
__device__ __forceinline__ void ldm_x4(uint32_t& r0, uint32_t& r1, uint32_t& r2, uint32_t& r3,
                                       uint32_t addr) {
    asm volatile("ldmatrix.sync.aligned.m8n8.x4.shared.b16 {%0,%1,%2,%3},[%4];\n"
                 : "=r"(r0), "=r"(r1), "=r"(r2), "=r"(r3) : "r"(addr));
}
__device__ __forceinline__ void ldm_x4_t(uint32_t& r0, uint32_t& r1, uint32_t& r2, uint32_t& r3,
                                         uint32_t addr) {
    asm volatile("ldmatrix.sync.aligned.m8n8.x4.trans.shared.b16 {%0,%1,%2,%3},[%4];\n"
                 : "=r"(r0), "=r"(r1), "=r"(r2), "=r"(r3) : "r"(addr));
}
__device__ __forceinline__ void ldm_x2(uint32_t& r0, uint32_t& r1, uint32_t addr) {
    asm volatile("ldmatrix.sync.aligned.m8n8.x2.shared.b16 {%0,%1},[%2];\n"
                 : "=r"(r0), "=r"(r1) : "r"(addr));
}
__device__ __forceinline__ void mma16816(float* c, uint32_t a0, uint32_t a1, uint32_t a2,
                                         uint32_t a3, uint32_t b0, uint32_t b1) {
    asm volatile("mma.sync.aligned.m16n8k16.row.col.f32.f16.f16.f32 "
                 "{%0,%1,%2,%3},{%4,%5,%6,%7},{%8,%9},{%0,%1,%2,%3};\n"
                 : "+f"(c[0]), "+f"(c[1]), "+f"(c[2]), "+f"(c[3])
                 : "r"(a0), "r"(a1), "r"(a2), "r"(a3), "r"(b0), "r"(b1));
}

// -------------------- weight convert: fp32 -> fp16 --------------------
__global__ __launch_bounds__(256)
void wconv_kernel(const float* __restrict__ w,
                  __half* __restrict__ hi, int n4) {
    int i = blockIdx.x * blockDim.x + threadIdx.x;
    if (i >= n4) return;
    float4 v = ((const float4*)w)[i];
    __half2 a(__float2half_rn(v.x), __float2half_rn(v.y));
    __half2 b(__float2half_rn(v.z), __float2half_rn(v.w));
    ((__half2*)hi)[i * 2]     = a;
    ((__half2*)hi)[i * 2 + 1] = b;
}

// -------------------- LayerNorm -> fp16 --------------------
__global__ __launch_bounds__(256)
void ln_kernel(const float* __restrict__ x,
               const float* __restrict__ w,
               const float* __restrict__ b,
               __half* __restrict__ yh) {
    int row = blockIdx.x;
    const float* xr = x + (size_t)row * CDIM;
    int t = threadIdx.x;
    float v0 = xr[t], v1 = xr[t + 256], v2 = xr[t + 512];
    float s  = v0 + v1 + v2;
    float ss = v0*v0 + v1*v1 + v2*v2;
    #pragma unroll
    for (int o = 16; o > 0; o >>= 1) {
        s  += __shfl_xor_sync(0xffffffffu, s,  o);
        ss += __shfl_xor_sync(0xffffffffu, ss, o);
    }
    __shared__ float sh_s[8], sh_ss[8];
    __shared__ float sh_mean, sh_rstd;
    int warp = t >> 5, lane = t & 31;
    if (lane == 0) { sh_s[warp] = s; sh_ss[warp] = ss; }
    __syncthreads();
    if (t == 0) {
        float ts = 0.f, tss = 0.f;
        #pragma unroll
        for (int i = 0; i < 8; i++) { ts += sh_s[i]; tss += sh_ss[i]; }
        float mean = ts * (1.0f / CDIM);
        float var  = tss * (1.0f / CDIM) - mean * mean;
        sh_mean = mean;
        sh_rstd = rsqrtf(var + 1e-5f);
    }
    __syncthreads();
    float mean = sh_mean, r = sh_rstd;
    size_t base = (size_t)row * CDIM;
    #pragma unroll
    for (int p = 0; p < 3; p++) {
        int c = t + p * 256;
        float v = (p == 0) ? v0 : (p == 1) ? v1 : v2;
        float y = (v - mean) * r * w[c] + b[c];
        yh[base + c] = __float2half_rn(y);
    }
}

// ========== tensor-core GEMM: Y[M,N] = X[M,K] @ W[N,K]^T ==========
// A, B single fp16 — one mma per fragment pair.
// EPI: 0 = none, 2 = +bias+residual, 3 = +bias+gelu    OUT: 0 = fp32, 1 = fp16
#define LDP   40                 // padded row stride (fp16 elems)
#define TILE  (128 * LDP)        // one operand tile in smem (elems)
#define STAGE (2 * TILE)         // A, B
#define GSMEM (2 * STAGE * 2)    // bytes (2 stages) = 40960

template<int EPI, int OUT>
__global__ __launch_bounds__(256)
void gemm_tc(const __half* __restrict__ A,
             const __half* __restrict__ B,
             const float* __restrict__ bias, const float* __restrict__ res,
             float* __restrict__ Y, __half* __restrict__ Yh,
             int Nout, int K) {
    extern __shared__ __align__(16) char smem_raw[];
    uint32_t sbase = (uint32_t)__cvta_generic_to_shared(smem_raw);

    const int t = threadIdx.x, lane = t & 31, warp = t >> 5;
    const int wm = (warp & 1) * 64;    // warp m-offset in tile
    const int wn = (warp >> 1) * 32;   // warp n-offset in tile
    const int m0 = blockIdx.y * 128, n0 = blockIdx.x * 128;

    float acc[4][4][4] = {};   // [m-frag][n-frag][c0..c3]

    auto issue = [&](int s, int k0) {
        uint32_t so = sbase + (uint32_t)(s * STAGE) * 2;
        #pragma unroll
        for (int p = 0; p < 2; p++) {
            int idx = t + p * 256;          // 0..511
            int row = idx >> 2;
            int c8  = (idx & 3) * 8;        // fp16 col offset
            size_t ga = (size_t)(m0 + row) * K + k0 + c8;
            size_t gb = (size_t)(n0 + row) * K + k0 + c8;
            uint32_t sm = (uint32_t)(row * LDP + c8) * 2;
            cp_async16(so + 0 * TILE * 2 + sm, A + ga);
            cp_async16(so + 1 * TILE * 2 + sm, B + gb);
        }
        cp_commit();
    };

    issue(0, 0);
    const int KT = K / 32;
    for (int kt = 0; kt < KT; kt++) {
        if (kt + 1 < KT) { issue((kt + 1) & 1, (kt + 1) * 32); cp_wait<1>(); }
        else             { cp_wait<0>(); }
        __syncthreads();

        uint32_t so = sbase + (uint32_t)((kt & 1) * STAGE) * 2;
        #pragma unroll
        for (int ks = 0; ks < 2; ks++) {
            uint32_t ah[4][4];
            #pragma unroll
            for (int i = 0; i < 4; i++) {
                uint32_t off = (uint32_t)((wm + i * 16 + (lane & 15)) * LDP +
                                          ks * 16 + (lane >> 4) * 8) * 2;
                ldm_x4(ah[i][0], ah[i][1], ah[i][2], ah[i][3], so + 0 * TILE * 2 + off);
            }
            uint32_t bh[4][2];
            #pragma unroll
            for (int j = 0; j < 4; j++) {
                int q = lane & 15;
                uint32_t off = (uint32_t)((wn + j * 8 + (q & 7)) * LDP +
                                          ks * 16 + (q >> 3) * 8) * 2;
                ldm_x2(bh[j][0], bh[j][1], so + 1 * TILE * 2 + off);
            }
            #pragma unroll
            for (int i = 0; i < 4; i++)
                #pragma unroll
                for (int j = 0; j < 4; j++)
                    mma16816(acc[i][j], ah[i][0], ah[i][1], ah[i][2], ah[i][3],
                             bh[j][0], bh[j][1]);
        }
        __syncthreads();
    }

    // ---- epilogue ----
    const int g = lane >> 2, tig = lane & 3;
    #pragma unroll
    for (int i = 0; i < 4; i++) {
        int rowa = m0 + wm + i * 16 + g;
        #pragma unroll
        for (int j = 0; j < 4; j++) {
            int coln = n0 + wn + j * 8 + tig * 2;
            float v[4] = { acc[i][j][0], acc[i][j][1], acc[i][j][2], acc[i][j][3] };
            if (EPI >= 2) {
                float b0 = bias[coln], b1 = bias[coln + 1];
                v[0] += b0; v[1] += b1; v[2] += b0; v[3] += b1;
            }
            size_t off0 = (size_t)rowa * Nout + coln;
            size_t off1 = (size_t)(rowa + 8) * Nout + coln;
            if (EPI == 2) {
                float2 r0 = *(const float2*)(res + off0);
                float2 r1 = *(const float2*)(res + off1);
                v[0] += r0.x; v[1] += r0.y; v[2] += r1.x; v[3] += r1.y;
            }
            if (EPI == 3) {
                #pragma unroll
                for (int e = 0; e < 4; e++)
                    v[e] = 0.5f * v[e] * (1.0f + erff(v[e] * 0.70710678118654752f));
            }
            if (OUT == 0) {
                *(float2*)(Y + off0) = make_float2(v[0], v[1]);
                *(float2*)(Y + off1) = make_float2(v[2], v[3]);
            } else {
                *(uint32_t*)(Yh + off0) = pack_h2(v[0], v[1]);
                *(uint32_t*)(Yh + off1) = pack_h2(v[2], v[3]);
            }
        }
    }
}

// ========== tensor-core flash attention (single-fp16 QKV) ==========
// S = QK^T: 1-term (inputs fp16-rounded; logit abs err ~2e-4 — budgeted).
// PV: 2-term (P exact 2-term fp16 split x V single).
// CTA: 128 q-rows, 8 warps, 64-key tiles, 2-stage K/V pipeline.
#define ALDP 72                         // padded row (64 d + 8)
#define QS_BYTES  (128 * ALDP * 2)      // Q array
#define KV_BYTES  (64 * ALDP * 2)       // one K or V array
#define ATTN_SMEM (QS_BYTES + 2 * 2 * KV_BYTES)   // 55296 B

__global__ __launch_bounds__(256)
void attn_tc(const __half* __restrict__ qkv_g,
             __half* __restrict__ oh) {
    extern __shared__ __align__(16) char smem_raw2[];
    uint32_t sb = (uint32_t)__cvta_generic_to_shared(smem_raw2);
    const int t = threadIdx.x, lane = t & 31, warp = t >> 5;
    const int bidx = blockIdx.y;
    const int b = bidx / NHEADS, hh = bidx % NHEADS;
    const int q0 = blockIdx.x * 128;
    const uint32_t QS = sb;

    #pragma unroll
    for (int p = 0; p < 4; p++) {
        int idx = t + p * 256;          // 0..1023
        int row = idx >> 3, ch = idx & 7;
        size_t g = (size_t)(b * NSEQ + q0 + row) * H3 + hh * 64 + ch * 8;
        cp_async16(QS + (uint32_t)(row * ALDP + ch * 8) * 2, qkv_g + g);
    }
    auto issueKV = [&](int s, int j0) {
        uint32_t base = sb + QS_BYTES + (uint32_t)s * 2 * KV_BYTES;
        #pragma unroll
        for (int p = 0; p < 2; p++) {
            int idx = t + p * 256;      // 0..511
            int row = idx >> 3, ch = idx & 7;
            size_t gk = (size_t)(b * NSEQ + j0 + row) * H3 + CDIM + hh * 64 + ch * 8;
            size_t gv = gk + CDIM;
            uint32_t so = (uint32_t)(row * ALDP + ch * 8) * 2;
            cp_async16(base + 0 * KV_BYTES + so, qkv_g + gk);   // K
            cp_async16(base + 1 * KV_BYTES + so, qkv_g + gv);   // V
        }
        cp_commit();
    };
    issueKV(0, 0);
    issueKV(1, 64);
    cp_wait<1>(); __syncthreads();

    uint32_t qf[4][4];
    const int wq = warp * 16;
    #pragma unroll
    for (int ks = 0; ks < 4; ks++) {
        uint32_t off = (uint32_t)((wq + (lane & 15)) * ALDP + ks * 16 + (lane >> 4) * 8) * 2;
        ldm_x4(qf[ks][0], qf[ks][1], qf[ks][2], qf[ks][3], QS + off);
    }

    float o[8][4] = {};
    float mrow[2] = { -1e30f, -1e30f };
    float lrow[2] = {};
    const int NT = NSEQ / 64;

    for (int kt = 0; kt < NT; kt++) {
        if (kt > 0) {
            if (kt < NT - 1) cp_wait<1>(); else cp_wait<0>();
            __syncthreads();
        }
        uint32_t KB = sb + QS_BYTES + (uint32_t)(kt & 1) * 2 * KV_BYTES;
        uint32_t KH = KB, VH = KB + KV_BYTES;

        // ---- S = Q K^T (1-term) ----
        float s[8][4] = {};
        #pragma unroll
        for (int j = 0; j < 8; j++) {
            uint32_t kb[8];
            uint32_t a0 = (uint32_t)((j * 8 + (lane & 7)) * ALDP + (lane >> 3) * 8) * 2;
            ldm_x4(kb[0], kb[1], kb[2], kb[3], KH + a0);
            ldm_x4(kb[4], kb[5], kb[6], kb[7], KH + a0 + 64);
            #pragma unroll
            for (int ks = 0; ks < 4; ks++)
                mma16816(s[j], qf[ks][0], qf[ks][1], qf[ks][2], qf[ks][3],
                         kb[ks * 2], kb[ks * 2 + 1]);
        }

        // ---- online softmax ----
        float mx0 = -1e30f, mx1 = -1e30f;
        #pragma unroll
        for (int j = 0; j < 8; j++) {
            #pragma unroll
            for (int c = 0; c < 4; c++) s[j][c] *= 0.125f;
            mx0 = fmaxf(mx0, fmaxf(s[j][0], s[j][1]));
            mx1 = fmaxf(mx1, fmaxf(s[j][2], s[j][3]));
        }
        mx0 = fmaxf(mx0, __shfl_xor_sync(0xffffffffu, mx0, 1));
        mx0 = fmaxf(mx0, __shfl_xor_sync(0xffffffffu, mx0, 2));
        mx1 = fmaxf(mx1, __shfl_xor_sync(0xffffffffu, mx1, 1));
        mx1 = fmaxf(mx1, __shfl_xor_sync(0xffffffffu, mx1, 2));
        float mn0 = fmaxf(mrow[0], mx0), mn1 = fmaxf(mrow[1], mx1);
        float al0 = __expf(mrow[0] - mn0), al1 = __expf(mrow[1] - mn1);
        float rs0 = 0.f, rs1 = 0.f;
        #pragma unroll
        for (int j = 0; j < 8; j++) {
            s[j][0] = __expf(s[j][0] - mn0);
            s[j][1] = __expf(s[j][1] - mn0);
            s[j][2] = __expf(s[j][2] - mn1);
            s[j][3] = __expf(s[j][3] - mn1);
            rs0 += s[j][0] + s[j][1];
            rs1 += s[j][2] + s[j][3];
        }
        rs0 += __shfl_xor_sync(0xffffffffu, rs0, 1);
        rs0 += __shfl_xor_sync(0xffffffffu, rs0, 2);
        rs1 += __shfl_xor_sync(0xffffffffu, rs1, 1);
        rs1 += __shfl_xor_sync(0xffffffffu, rs1, 2);
        lrow[0] = lrow[0] * al0 + rs0;
        lrow[1] = lrow[1] * al1 + rs1;
        mrow[0] = mn0; mrow[1] = mn1;
        #pragma unroll
        for (int j = 0; j < 8; j++) {
            o[j][0] *= al0; o[j][1] *= al0;
            o[j][2] *= al1; o[j][3] *= al1;
        }

        // ---- pack P into A-fragments (hi + lo, exact split) ----
        uint32_t ph[4][4], pl[4][4];
        #pragma unroll
        for (int ks = 0; ks < 4; ks++) {
            split_pack2(s[2*ks][0],   s[2*ks][1],   ph[ks][0], pl[ks][0]);
            split_pack2(s[2*ks][2],   s[2*ks][3],   ph[ks][1], pl[ks][1]);
            split_pack2(s[2*ks+1][0], s[2*ks+1][1], ph[ks][2], pl[ks][2]);
            split_pack2(s[2*ks+1][2], s[2*ks+1][3], ph[ks][3], pl[ks][3]);
        }

        // ---- O += P V (2-term: PhV + PlV), V via ldmatrix.trans ----
        #pragma unroll
        for (int ks = 0; ks < 4; ks++) {
            #pragma unroll
            for (int jp = 0; jp < 4; jp++) {
                uint32_t vh[4];
                uint32_t addr = (uint32_t)(
                    (ks * 16 + (lane & 7) + ((lane >> 3) & 1) * 8) * ALDP +
                    jp * 16 + (lane >> 4) * 8) * 2;
                ldm_x4_t(vh[0], vh[1], vh[2], vh[3], VH + addr);
                mma16816(o[jp*2],   ph[ks][0], ph[ks][1], ph[ks][2], ph[ks][3], vh[0], vh[1]);
                mma16816(o[jp*2],   pl[ks][0], pl[ks][1], pl[ks][2], pl[ks][3], vh[0], vh[1]);
                mma16816(o[jp*2+1], ph[ks][0], ph[ks][1], ph[ks][2], ph[ks][3], vh[2], vh[3]);
                mma16816(o[jp*2+1], pl[ks][0], pl[ks][1], pl[ks][2], pl[ks][3], vh[2], vh[3]);
            }
        }

        __syncthreads();
        if (kt + 2 < NT) issueKV(kt & 1, (kt + 2) * 64);
    }

    // ---- epilogue: normalize, store fp16 ----
    float inv0 = 1.0f / lrow[0], inv1 = 1.0f / lrow[1];
    int r0 = q0 + wq + (lane >> 2);
    #pragma unroll
    for (int j = 0; j < 8; j++) {
        int col = hh * 64 + j * 8 + (lane & 3) * 2;
        size_t off0 = (size_t)(b * NSEQ + r0) * CDIM + col;
        size_t off1 = (size_t)(b * NSEQ + r0 + 8) * CDIM + col;
        *(uint32_t*)(oh + off0) = pack_h2(o[j][0] * inv0, o[j][1] * inv0);
        *(uint32_t*)(oh + off1) = pack_h2(o[j][2] * inv1, o[j][3] * inv1);
    }
}

// -------------------- launch --------------------
extern "C" void kernel_launch(void* const* d_in, const int* in_sizes, int n_in,
                              void* d_out, int out_size) {
    const float* x      = (const float*)d_in[0];
    const float* qkv_w  = (const float*)d_in[1];
    const float* proj_w = (const float*)d_in[2];
    const float* proj_b = (const float*)d_in[3];
    const float* n1w    = (const float*)d_in[4];
    const float* n1b    = (const float*)d_in[5];
    const float* n2w    = (const float*)d_in[6];
    const float* n2b    = (const float*)d_in[7];
    const float* fc1w   = (const float*)d_in[8];
    const float* fc1b   = (const float*)d_in[9];
    const float* fc2w   = (const float*)d_in[10];
    const float* fc2b   = (const float*)d_in[11];
    float* out = (float*)d_out;

    static bool s_init = false;
    static __half *xh, *qk, *ah, *mh, *wq, *wp, *w1, *w2;
    static float *x1;
    if (!s_init) {
        cudaGetSymbolAddress((void**)&xh, g_xh);
        cudaGetSymbolAddress((void**)&qk, g_qkv);
        cudaGetSymbolAddress((void**)&ah, g_ah);
        cudaGetSymbolAddress((void**)&x1, g_x1);
        cudaGetSymbolAddress((void**)&mh, g_mh);
        cudaGetSymbolAddress((void**)&wq, g_wqkv);
        cudaGetSymbolAddress((void**)&wp, g_wprj);
        cudaGetSymbolAddress((void**)&w1, g_wf1);
        cudaGetSymbolAddress((void**)&w2, g_wf2);
        cudaFuncSetAttribute(attn_tc,
                             cudaFuncAttributeMaxDynamicSharedMemorySize, ATTN_SMEM);
        cudaFuncSetAttribute(gemm_tc<0,1>,
                             cudaFuncAttributeMaxDynamicSharedMemorySize, GSMEM);
        cudaFuncSetAttribute(gemm_tc<2,0>,
                             cudaFuncAttributeMaxDynamicSharedMemorySize, GSMEM);
        cudaFuncSetAttribute(gemm_tc<3,1>,
                             cudaFuncAttributeMaxDynamicSharedMemorySize, GSMEM);
        s_init = true;
    }
    (void)in_sizes; (void)n_in; (void)out_size;

    dim3 thr(256);

    // weight converts (fp32 -> fp16)
    wconv_kernel<<<(H3*CDIM/4 + 255)/256, thr>>>(qkv_w,  wq, H3*CDIM/4);
    wconv_kernel<<<(CDIM*CDIM/4 + 255)/256, thr>>>(proj_w, wp, CDIM*CDIM/4);
    wconv_kernel<<<(HID*CDIM/4 + 255)/256, thr>>>(fc1w,  w1, HID*CDIM/4);
    wconv_kernel<<<(CDIM*HID/4 + 255)/256, thr>>>(fc2w,  w2, CDIM*HID/4);

    // 1. LN1 -> fp16
    ln_kernel<<<MDIM, thr>>>(x, n1w, n1b, xh);
    // 2. qkv = h @ qkv_w^T -> fp16
    gemm_tc<0,1><<<dim3(H3/128, MDIM/128), thr, GSMEM>>>(
        xh, wq, nullptr, nullptr, nullptr, qk, H3, CDIM);
    // 3. attention -> fp16
    attn_tc<<<dim3(NSEQ/128, BATCH*NHEADS), thr, ATTN_SMEM>>>(qk, ah);
    // 4. x1 = x + attn @ proj_w^T + proj_b   (fp32)
    gemm_tc<2,0><<<dim3(CDIM/128, MDIM/128), thr, GSMEM>>>(
        ah, wp, proj_b, x, x1, nullptr, CDIM, CDIM);
    // 5. LN2 -> fp16
    ln_kernel<<<MDIM, thr>>>(x1, n2w, n2b, xh);
    // 6. mlp = gelu(h2 @ fc1_w^T + fc1_b) -> fp16
    gemm_tc<3,1><<<dim3(HID/128, MDIM/128), thr, GSMEM>>>(
        xh, w1, fc1b, nullptr, nullptr, mh, HID, CDIM);
    // 7. out = x1 + mlp @ fc2_w^T + fc2_b   (fp32)
    gemm_tc<2,0><<<dim3(CDIM/128, MDIM/128), thr, GSMEM>>>(
        mh, w2, fc2b, x1, out, nullptr, CDIM, HID);
}

// round 17
// speedup vs baseline: 8.6571x; 1.2674x over previous
#include <cuda_runtime.h>
#include <cuda_fp16.h>
#include <math.h>
#include <stdint.h>

// Problem constants
#define BATCH   4
#define NSEQ    2048
#define CDIM    768
#define NHEADS  12
#define H3      2304      // 3*CDIM
#define HID     3072      // 4*CDIM
#define MDIM    (BATCH*NSEQ)   // 8192 rows

// -------------------- scratch (no allocations allowed) --------------------
__device__ __half g_xh [MDIM * CDIM];   // LN out (fp16)
__device__ __half g_qkv[MDIM * H3];     // qkv (fp16)
__device__ __half g_ah [MDIM * CDIM];   // attn out (fp16)
__device__ float  g_x1 [MDIM * CDIM];   // residual 1 (fp32)
__device__ __half g_mh [MDIM * HID];    // mlp post-gelu (fp16)
__device__ __half g_wqkv[H3 * CDIM];
__device__ __half g_wprj[CDIM * CDIM];
__device__ __half g_wf1 [HID * CDIM];
__device__ __half g_wf2 [CDIM * HID];

// -------------------- small helpers --------------------
__device__ __forceinline__ uint32_t pack_h2(float x, float y) {
    __half2 H(__float2half_rn(x), __float2half_rn(y));
    return *(uint32_t*)&H;
}
__device__ __forceinline__ void cp_async16(uint32_t dst, const void* src) {
    asm volatile("cp.async.cg.shared.global [%0], [%1], 16;\n" :: "r"(dst), "l"(src));
}
__device__ __forceinline__ void cp_commit() {
    asm volatile("cp.async.commit_group;\n");
}
template<int N> __device__ __forceinline__ void cp_wait() {
    asm volatile("cp.async.wait_group %0;\n" :: "n"(N));
}
__device__ __forceinline__ void ldm_x4(uint32_t& r0, uint32_t& r1, uint32_t& r2, uint32_t& r3,
                                       uint32_t addr) {
    asm volatile("ldmatrix.sync.aligned.m8n8.x4.shared.b16 {%0,%1,%2,%3},[%4];\n"
                 : "=r"(r0), "=r"(r1), "=r"(r2), "=r"(r3) : "r"(addr));
}
__device__ __forceinline__ void ldm_x4_t(uint32_t& r0, uint32_t& r1, uint32_t& r2, uint32_t& r3,
                                         uint32_t addr) {
    asm volatile("ldmatrix.sync.aligned.m8n8.x4.trans.shared.b16 {%0,%1,%2,%3},[%4];\n"
                 : "=r"(r0), "=r"(r1), "=r"(r2), "=r"(r3) : "r"(addr));
}
__device__ __forceinline__ void ldm_x2(uint32_t& r0, uint32_t& r1, uint32_t addr) {
    asm volatile("ldmatrix.sync.aligned.m8n8.x2.shared.b16 {%0,%1},[%2];\n"
                 : "=r"(r0), "=r"(r1) : "r"(addr));
}
__device__ __forceinline__ void mma16816(float* c, uint32_t a0, uint32_t a1, uint32_t a2,
                                         uint32_t a3, uint32_t b0, uint32_t b1) {
    asm volatile("mma.sync.aligned.m16n8k16.row.col.f32.f16.f16.f32 "
                 "{%0,%1,%2,%3},{%4,%5,%6,%7},{%8,%9},{%0,%1,%2,%3};\n"
                 : "+f"(c[0]), "+f"(c[1]), "+f"(c[2]), "+f"(c[3])
                 : "r"(a0), "r"(a1), "r"(a2), "r"(a3), "r"(b0), "r"(b1));
}

// -------------------- fused weight convert: all 4 weights, one launch --------
#define WSEG0 (H3*CDIM/4)
#define WSEG1 (WSEG0 + CDIM*CDIM/4)
#define WSEG2 (WSEG1 + HID*CDIM/4)
#define WSEG3 (WSEG2 + CDIM*HID/4)

__global__ __launch_bounds__(256)
void wconv_all(const float* __restrict__ w0, const float* __restrict__ w1,
               const float* __restrict__ w2, const float* __restrict__ w3,
               __half* __restrict__ o0, __half* __restrict__ o1,
               __half* __restrict__ o2, __half* __restrict__ o3) {
    int i = blockIdx.x * blockDim.x + threadIdx.x;
    const float* w; __half* o; int j;
    if      (i < WSEG0) { w = w0; o = o0; j = i; }
    else if (i < WSEG1) { w = w1; o = o1; j = i - WSEG0; }
    else if (i < WSEG2) { w = w2; o = o2; j = i - WSEG1; }
    else if (i < WSEG3) { w = w3; o = o3; j = i - WSEG2; }
    else return;
    float4 v = ((const float4*)w)[j];
    ((__half2*)o)[j * 2]     = __half2(__float2half_rn(v.x), __float2half_rn(v.y));
    ((__half2*)o)[j * 2 + 1] = __half2(__float2half_rn(v.z), __float2half_rn(v.w));
}

// -------------------- LayerNorm -> fp16 --------------------
__global__ __launch_bounds__(256)
void ln_kernel(const float* __restrict__ x,
               const float* __restrict__ w,
               const float* __restrict__ b,
               __half* __restrict__ yh) {
    int row = blockIdx.x;
    const float* xr = x + (size_t)row * CDIM;
    int t = threadIdx.x;
    float v0 = xr[t], v1 = xr[t + 256], v2 = xr[t + 512];
    float s  = v0 + v1 + v2;
    float ss = v0*v0 + v1*v1 + v2*v2;
    #pragma unroll
    for (int o = 16; o > 0; o >>= 1) {
        s  += __shfl_xor_sync(0xffffffffu, s,  o);
        ss += __shfl_xor_sync(0xffffffffu, ss, o);
    }
    __shared__ float sh_s[8], sh_ss[8];
    __shared__ float sh_mean, sh_rstd;
    int warp = t >> 5, lane = t & 31;
    if (lane == 0) { sh_s[warp] = s; sh_ss[warp] = ss; }
    __syncthreads();
    if (t == 0) {
        float ts = 0.f, tss = 0.f;
        #pragma unroll
        for (int i = 0; i < 8; i++) { ts += sh_s[i]; tss += sh_ss[i]; }
        float mean = ts * (1.0f / CDIM);
        float var  = tss * (1.0f / CDIM) - mean * mean;
        sh_mean = mean;
        sh_rstd = rsqrtf(var + 1e-5f);
    }
    __syncthreads();
    float mean = sh_mean, r = sh_rstd;
    size_t base = (size_t)row * CDIM;
    #pragma unroll
    for (int p = 0; p < 3; p++) {
        int c = t + p * 256;
        float v = (p == 0) ? v0 : (p == 1) ? v1 : v2;
        yh[base + c] = __float2half_rn((v - mean) * r * w[c] + b[c]);
    }
}

// ========== tensor-core GEMM: Y[M,N] = X[M,K] @ W[N,K]^T ==========
// Single-fp16 operands, one mma per fragment pair. K-chunk = 64.
// EPI: 0 = none, 2 = +bias+residual, 3 = +bias+gelu    OUT: 0 = fp32, 1 = fp16
#define LDP   72                 // padded row stride (fp16 elems) for 64-col tiles
#define TILE  (128 * LDP)        // one operand tile in smem (elems)
#define STAGE (2 * TILE)         // A, B
#define GSMEM (2 * STAGE * 2)    // bytes (2 stages) = 73728

template<int EPI, int OUT>
__global__ __launch_bounds__(256)
void gemm_tc(const __half* __restrict__ A,
             const __half* __restrict__ B,
             const float* __restrict__ bias, const float* __restrict__ res,
             float* __restrict__ Y, __half* __restrict__ Yh,
             int Nout, int K) {
    extern __shared__ __align__(16) char smem_raw[];
    uint32_t sbase = (uint32_t)__cvta_generic_to_shared(smem_raw);

    const int t = threadIdx.x, lane = t & 31, warp = t >> 5;
    const int wm = (warp & 1) * 64;
    const int wn = (warp >> 1) * 32;
    const int m0 = blockIdx.y * 128, n0 = blockIdx.x * 128;

    float acc[4][4][4] = {};

    // one K-chunk (64 cols): 1024 16B-chunks per tile, 4 per thread per tile
    auto issue = [&](int s, int k0) {
        uint32_t so = sbase + (uint32_t)(s * STAGE) * 2;
        #pragma unroll
        for (int p = 0; p < 4; p++) {
            int idx = t + p * 256;          // 0..1023
            int row = idx >> 3, ch = idx & 7;
            size_t ga = (size_t)(m0 + row) * K + k0 + ch * 8;
            size_t gb = (size_t)(n0 + row) * K + k0 + ch * 8;
            uint32_t sm = (uint32_t)(row * LDP + ch * 8) * 2;
            cp_async16(so + 0 * TILE * 2 + sm, A + ga);
            cp_async16(so + 1 * TILE * 2 + sm, B + gb);
        }
        cp_commit();
    };

    issue(0, 0);
    const int KT = K / 64;
    for (int kt = 0; kt < KT; kt++) {
        if (kt + 1 < KT) { issue((kt + 1) & 1, (kt + 1) * 64); cp_wait<1>(); }
        else             { cp_wait<0>(); }
        __syncthreads();

        uint32_t so = sbase + (uint32_t)((kt & 1) * STAGE) * 2;
        #pragma unroll
        for (int ks = 0; ks < 4; ks++) {
            uint32_t ah[4][4];
            #pragma unroll
            for (int i = 0; i < 4; i++) {
                uint32_t off = (uint32_t)((wm + i * 16 + (lane & 15)) * LDP +
                                          ks * 16 + (lane >> 4) * 8) * 2;
                ldm_x4(ah[i][0], ah[i][1], ah[i][2], ah[i][3], so + 0 * TILE * 2 + off);
            }
            uint32_t bh[4][2];
            #pragma unroll
            for (int j = 0; j < 4; j++) {
                int q = lane & 15;
                uint32_t off = (uint32_t)((wn + j * 8 + (q & 7)) * LDP +
                                          ks * 16 + (q >> 3) * 8) * 2;
                ldm_x2(bh[j][0], bh[j][1], so + 1 * TILE * 2 + off);
            }
            #pragma unroll
            for (int i = 0; i < 4; i++)
                #pragma unroll
                for (int j = 0; j < 4; j++)
                    mma16816(acc[i][j], ah[i][0], ah[i][1], ah[i][2], ah[i][3],
                             bh[j][0], bh[j][1]);
        }
        __syncthreads();
    }

    // ---- epilogue ----
    const int g = lane >> 2, tig = lane & 3;
    #pragma unroll
    for (int i = 0; i < 4; i++) {
        int rowa = m0 + wm + i * 16 + g;
        #pragma unroll
        for (int j = 0; j < 4; j++) {
            int coln = n0 + wn + j * 8 + tig * 2;
            float v[4] = { acc[i][j][0], acc[i][j][1], acc[i][j][2], acc[i][j][3] };
            if (EPI >= 2) {
                float b0 = bias[coln], b1 = bias[coln + 1];
                v[0] += b0; v[1] += b1; v[2] += b0; v[3] += b1;
            }
            size_t off0 = (size_t)rowa * Nout + coln;
            size_t off1 = (size_t)(rowa + 8) * Nout + coln;
            if (EPI == 2) {
                float2 r0 = *(const float2*)(res + off0);
                float2 r1 = *(const float2*)(res + off1);
                v[0] += r0.x; v[1] += r0.y; v[2] += r1.x; v[3] += r1.y;
            }
            if (EPI == 3) {
                #pragma unroll
                for (int e = 0; e < 4; e++)
                    v[e] = 0.5f * v[e] * (1.0f + erff(v[e] * 0.70710678118654752f));
            }
            if (OUT == 0) {
                *(float2*)(Y + off0) = make_float2(v[0], v[1]);
                *(float2*)(Y + off1) = make_float2(v[2], v[3]);
            } else {
                *(uint32_t*)(Yh + off0) = pack_h2(v[0], v[1]);
                *(uint32_t*)(Yh + off1) = pack_h2(v[2], v[3]);
            }
        }
    }
}

// ========== tensor-core flash attention (single-fp16, 1-term S, 1-term PV) ====
#define ALDP 72
#define QS_BYTES  (128 * ALDP * 2)
#define KV_BYTES  (64 * ALDP * 2)
#define ATTN_SMEM (QS_BYTES + 2 * 2 * KV_BYTES)   // 55296 B

__global__ __launch_bounds__(256)
void attn_tc(const __half* __restrict__ qkv_g,
             __half* __restrict__ oh) {
    extern __shared__ __align__(16) char smem_raw2[];
    uint32_t sb = (uint32_t)__cvta_generic_to_shared(smem_raw2);
    const int t = threadIdx.x, lane = t & 31, warp = t >> 5;
    const int bidx = blockIdx.y;
    const int b = bidx / NHEADS, hh = bidx % NHEADS;
    const int q0 = blockIdx.x * 128;
    const uint32_t QS = sb;

    #pragma unroll
    for (int p = 0; p < 4; p++) {
        int idx = t + p * 256;
        int row = idx >> 3, ch = idx & 7;
        size_t g = (size_t)(b * NSEQ + q0 + row) * H3 + hh * 64 + ch * 8;
        cp_async16(QS + (uint32_t)(row * ALDP + ch * 8) * 2, qkv_g + g);
    }
    auto issueKV = [&](int s, int j0) {
        uint32_t base = sb + QS_BYTES + (uint32_t)s * 2 * KV_BYTES;
        #pragma unroll
        for (int p = 0; p < 2; p++) {
            int idx = t + p * 256;
            int row = idx >> 3, ch = idx & 7;
            size_t gk = (size_t)(b * NSEQ + j0 + row) * H3 + CDIM + hh * 64 + ch * 8;
            size_t gv = gk + CDIM;
            uint32_t so = (uint32_t)(row * ALDP + ch * 8) * 2;
            cp_async16(base + 0 * KV_BYTES + so, qkv_g + gk);   // K
            cp_async16(base + 1 * KV_BYTES + so, qkv_g + gv);   // V
        }
        cp_commit();
    };
    issueKV(0, 0);
    issueKV(1, 64);
    cp_wait<1>(); __syncthreads();

    uint32_t qf[4][4];
    const int wq = warp * 16;
    #pragma unroll
    for (int ks = 0; ks < 4; ks++) {
        uint32_t off = (uint32_t)((wq + (lane & 15)) * ALDP + ks * 16 + (lane >> 4) * 8) * 2;
        ldm_x4(qf[ks][0], qf[ks][1], qf[ks][2], qf[ks][3], QS + off);
    }

    float o[8][4] = {};
    float mrow[2] = { -1e30f, -1e30f };
    float lrow[2] = {};
    const int NT = NSEQ / 64;

    for (int kt = 0; kt < NT; kt++) {
        if (kt > 0) {
            if (kt < NT - 1) cp_wait<1>(); else cp_wait<0>();
            __syncthreads();
        }
        uint32_t KB = sb + QS_BYTES + (uint32_t)(kt & 1) * 2 * KV_BYTES;
        uint32_t KH = KB, VH = KB + KV_BYTES;

        // ---- S = Q K^T ----
        float s[8][4] = {};
        #pragma unroll
        for (int j = 0; j < 8; j++) {
            uint32_t kb[8];
            uint32_t a0 = (uint32_t)((j * 8 + (lane & 7)) * ALDP + (lane >> 3) * 8) * 2;
            ldm_x4(kb[0], kb[1], kb[2], kb[3], KH + a0);
            ldm_x4(kb[4], kb[5], kb[6], kb[7], KH + a0 + 64);
            #pragma unroll
            for (int ks = 0; ks < 4; ks++)
                mma16816(s[j], qf[ks][0], qf[ks][1], qf[ks][2], qf[ks][3],
                         kb[ks * 2], kb[ks * 2 + 1]);
        }

        // ---- online softmax ----
        float mx0 = -1e30f, mx1 = -1e30f;
        #pragma unroll
        for (int j = 0; j < 8; j++) {
            #pragma unroll
            for (int c = 0; c < 4; c++) s[j][c] *= 0.125f;
            mx0 = fmaxf(mx0, fmaxf(s[j][0], s[j][1]));
            mx1 = fmaxf(mx1, fmaxf(s[j][2], s[j][3]));
        }
        mx0 = fmaxf(mx0, __shfl_xor_sync(0xffffffffu, mx0, 1));
        mx0 = fmaxf(mx0, __shfl_xor_sync(0xffffffffu, mx0, 2));
        mx1 = fmaxf(mx1, __shfl_xor_sync(0xffffffffu, mx1, 1));
        mx1 = fmaxf(mx1, __shfl_xor_sync(0xffffffffu, mx1, 2));
        float mn0 = fmaxf(mrow[0], mx0), mn1 = fmaxf(mrow[1], mx1);
        float al0 = __expf(mrow[0] - mn0), al1 = __expf(mrow[1] - mn1);
        float rs0 = 0.f, rs1 = 0.f;
        #pragma unroll
        for (int j = 0; j < 8; j++) {
            s[j][0] = __expf(s[j][0] - mn0);
            s[j][1] = __expf(s[j][1] - mn0);
            s[j][2] = __expf(s[j][2] - mn1);
            s[j][3] = __expf(s[j][3] - mn1);
            rs0 += s[j][0] + s[j][1];
            rs1 += s[j][2] + s[j][3];
        }
        rs0 += __shfl_xor_sync(0xffffffffu, rs0, 1);
        rs0 += __shfl_xor_sync(0xffffffffu, rs0, 2);
        rs1 += __shfl_xor_sync(0xffffffffu, rs1, 1);
        rs1 += __shfl_xor_sync(0xffffffffu, rs1, 2);
        lrow[0] = lrow[0] * al0 + rs0;
        lrow[1] = lrow[1] * al1 + rs1;
        mrow[0] = mn0; mrow[1] = mn1;
        #pragma unroll
        for (int j = 0; j < 8; j++) {
            o[j][0] *= al0; o[j][1] *= al0;
            o[j][2] *= al1; o[j][3] *= al1;
        }

        // ---- pack P (hi only) ----
        uint32_t ph[4][4];
        #pragma unroll
        for (int ks = 0; ks < 4; ks++) {
            ph[ks][0] = pack_h2(s[2*ks][0],   s[2*ks][1]);
            ph[ks][1] = pack_h2(s[2*ks][2],   s[2*ks][3]);
            ph[ks][2] = pack_h2(s[2*ks+1][0], s[2*ks+1][1]);
            ph[ks][3] = pack_h2(s[2*ks+1][2], s[2*ks+1][3]);
        }

        // ---- O += P V (1-term), V via ldmatrix.trans ----
        #pragma unroll
        for (int ks = 0; ks < 4; ks++) {
            #pragma unroll
            for (int jp = 0; jp < 4; jp++) {
                uint32_t vh[4];
                uint32_t addr = (uint32_t)(
                    (ks * 16 + (lane & 7) + ((lane >> 3) & 1) * 8) * ALDP +
                    jp * 16 + (lane >> 4) * 8) * 2;
                ldm_x4_t(vh[0], vh[1], vh[2], vh[3], VH + addr);
                mma16816(o[jp*2],   ph[ks][0], ph[ks][1], ph[ks][2], ph[ks][3], vh[0], vh[1]);
                mma16816(o[jp*2+1], ph[ks][0], ph[ks][1], ph[ks][2], ph[ks][3], vh[2], vh[3]);
            }
        }

        __syncthreads();
        if (kt + 2 < NT) issueKV(kt & 1, (kt + 2) * 64);
    }

    // ---- epilogue ----
    float inv0 = 1.0f / lrow[0], inv1 = 1.0f / lrow[1];
    int r0 = q0 + wq + (lane >> 2);
    #pragma unroll
    for (int j = 0; j < 8; j++) {
        int col = hh * 64 + j * 8 + (lane & 3) * 2;
        size_t off0 = (size_t)(b * NSEQ + r0) * CDIM + col;
        size_t off1 = (size_t)(b * NSEQ + r0 + 8) * CDIM + col;
        *(uint32_t*)(oh + off0) = pack_h2(o[j][0] * inv0, o[j][1] * inv0);
        *(uint32_t*)(oh + off1) = pack_h2(o[j][2] * inv1, o[j][3] * inv1);
    }
}

// -------------------- launch --------------------
extern "C" void kernel_launch(void* const* d_in, const int* in_sizes, int n_in,
                              void* d_out, int out_size) {
    const float* x      = (const float*)d_in[0];
    const float* qkv_w  = (const float*)d_in[1];
    const float* proj_w = (const float*)d_in[2];
    const float* proj_b = (const float*)d_in[3];
    const float* n1w    = (const float*)d_in[4];
    const float* n1b    = (const float*)d_in[5];
    const float* n2w    = (const float*)d_in[6];
    const float* n2b    = (const float*)d_in[7];
    const float* fc1w   = (const float*)d_in[8];
    const float* fc1b   = (const float*)d_in[9];
    const float* fc2w   = (const float*)d_in[10];
    const float* fc2b   = (const float*)d_in[11];
    float* out = (float*)d_out;

    static bool s_init = false;
    static __half *xh, *qk, *ah, *mh, *wq, *wp, *w1, *w2;
    static float *x1;
    if (!s_init) {
        cudaGetSymbolAddress((void**)&xh, g_xh);
        cudaGetSymbolAddress((void**)&qk, g_qkv);
        cudaGetSymbolAddress((void**)&ah, g_ah);
        cudaGetSymbolAddress((void**)&x1, g_x1);
        cudaGetSymbolAddress((void**)&mh, g_mh);
        cudaGetSymbolAddress((void**)&wq, g_wqkv);
        cudaGetSymbolAddress((void**)&wp, g_wprj);
        cudaGetSymbolAddress((void**)&w1, g_wf1);
        cudaGetSymbolAddress((void**)&w2, g_wf2);
        cudaFuncSetAttribute(attn_tc,
                             cudaFuncAttributeMaxDynamicSharedMemorySize, ATTN_SMEM);
        cudaFuncSetAttribute(gemm_tc<0,1>,
                             cudaFuncAttributeMaxDynamicSharedMemorySize, GSMEM);
        cudaFuncSetAttribute(gemm_tc<2,0>,
                             cudaFuncAttributeMaxDynamicSharedMemorySize, GSMEM);
        cudaFuncSetAttribute(gemm_tc<3,1>,
                             cudaFuncAttributeMaxDynamicSharedMemorySize, GSMEM);
        s_init = true;
    }
    (void)in_sizes; (void)n_in; (void)out_size;

    dim3 thr(256);

    // all weight converts in one launch
    wconv_all<<<(WSEG3 + 255) / 256, thr>>>(qkv_w, proj_w, fc1w, fc2w,
                                            wq, wp, w1, w2);

    // 1. LN1 -> fp16
    ln_kernel<<<MDIM, thr>>>(x, n1w, n1b, xh);
    // 2. qkv = h @ qkv_w^T -> fp16
    gemm_tc<0,1><<<dim3(H3/128, MDIM/128), thr, GSMEM>>>(
        xh, wq, nullptr, nullptr, nullptr, qk, H3, CDIM);
    // 3. attention -> fp16
    attn_tc<<<dim3(NSEQ/128, BATCH*NHEADS), thr, ATTN_SMEM>>>(qk, ah);
    // 4. x1 = x + attn @ proj_w^T + proj_b   (fp32)
    gemm_tc<2,0><<<dim3(CDIM/128, MDIM/128), thr, GSMEM>>>(
        ah, wp, proj_b, x, x1, nullptr, CDIM, CDIM);
    // 5. LN2 -> fp16
    ln_kernel<<<MDIM, thr>>>(x1, n2w, n2b, xh);
    // 6. mlp = gelu(h2 @ fc1_w^T + fc1_b) -> fp16
    gemm_tc<3,1><<<dim3(HID/128, MDIM/128), thr, GSMEM>>>(
        xh, w1, fc1b, nullptr, nullptr, mh, HID, CDIM);
    // 7. out = x1 + mlp @ fc2_w^T + fc2_b   (fp32)
    gemm_tc<2,0><<<dim3(CDIM/128, MDIM/128), thr, GSMEM>>>(
        mh, w2, fc2b, x1, out, nullptr, CDIM, HID);
}